// round 12
// baseline (speedup 1.0000x reference)
#include <cuda_runtime.h>
#include <math.h>
#include <stdint.h>

// Problem constants
#define BB   4
#define LL   2048
#define DD   512
#define HH   8
#define HD   64
#define DFF  2048
#define MR   (BB*LL)   // 8192 rows

// ---------------- scratch (device globals: allocation-free) ----------------
__device__ float g_qkv [MR * 3 * DD];
__device__ float g_vals[MR * DD];
__device__ float g_tmp [MR * DD];
__device__ float g_x1  [MR * DD];
__device__ float g_ff  [MR * DFF];
__device__ int   g_mflag[16 * 32];   // per (128-row qtile, 64-col stile) all-ones flag

// ---------------------------------------------------------------------------
// tf32 + async helpers (supported on base sm_100)
// ---------------------------------------------------------------------------
__device__ __forceinline__ uint32_t f2tf32(float x) {
    uint32_t r;
    asm("cvt.rna.tf32.f32 %0, %1;" : "=r"(r) : "f"(x));
    return r;
}
__device__ __forceinline__ uint32_t smem_u32(const void* p) {
    uint32_t a;
    asm("{ .reg .u64 t; cvta.to.shared.u64 t, %1; cvt.u32.u64 %0, t; }"
        : "=r"(a) : "l"(p));
    return a;
}

#define MMA_TF32(d, a, b)                                                      \
    asm volatile("mma.sync.aligned.m16n8k8.row.col.f32.tf32.tf32.f32 "         \
        "{%0,%1,%2,%3}, {%4,%5,%6,%7}, {%8,%9}, {%0,%1,%2,%3};"                \
        : "+f"((d)[0]), "+f"((d)[1]), "+f"((d)[2]), "+f"((d)[3])               \
        : "r"((a)[0]), "r"((a)[1]), "r"((a)[2]), "r"((a)[3]),                  \
          "r"((b)[0]), "r"((b)[1]))

#define CP_ASYNC16(dst, src)                                                   \
    asm volatile("cp.async.cg.shared.global [%0], [%1], 16;"                   \
        :: "r"(dst), "l"(src) : "memory")
#define CP_COMMIT() asm volatile("cp.async.commit_group;" ::: "memory")
#define CP_WAIT(n)  asm volatile("cp.async.wait_group %0;" :: "n"(n) : "memory")

// ---------------------------------------------------------------------------
// mma.sync tf32 GEMM v3: BK=32, 3-stage cp.async pipeline, RAW fp32 operands.
// Half the barrier/wait envelopes of v2 (stage count halves); each stage
// carries 128 MMAs/warp. Truncation bias cancelled by acc*1.000704 in the
// epilogue (R11-validated). GPAD=36 -> fragment loads conflict-free
// ((4*grp+qd) mod 32 distinct). Depth-2 issue over 3 buffers: issue(s+2)
// never touches the buffer being computed.
// ---------------------------------------------------------------------------
#define GPAD 36
#define GTILE (128 * GPAD)                 // words per tensor per stage
#define GSTG 3
#define GEMM_SMEM (GSTG * 2 * GTILE * 4)   // 110592 bytes

template<int RELU>
__global__ __launch_bounds__(256, 2)
void mma_gemm(const float* __restrict__ A, const float* __restrict__ W,
              const float* __restrict__ bias, float* __restrict__ C,
              int M, int N, int K)
{
    extern __shared__ float gsm[];

    const int tid  = threadIdx.x;
    const int wid  = tid >> 5, lane = tid & 31;
    const int grp  = lane >> 2, qd = lane & 3;
    const int wm   = (wid & 1) * 64;
    const int wn   = (wid >> 1) * 32;
    const int bm   = blockIdx.y * 128;
    const int bn   = blockIdx.x * 128;

    const int lrow = tid >> 1;             // 0..127
    const int lk16 = (tid & 1) * 16;       // 0 or 16 (half-row of 32 floats)

    const float* Ap = A + (size_t)(bm + lrow) * K + lk16;
    const float* Wp = W + (size_t)(bn + lrow) * K + lk16;

    uint32_t sAw[GSTG], sBw[GSTG];
    #pragma unroll
    for (int b = 0; b < GSTG; ++b) {
        sAw[b] = smem_u32(gsm + (2 * b    ) * GTILE + lrow * GPAD + lk16);
        sBw[b] = smem_u32(gsm + (2 * b + 1) * GTILE + lrow * GPAD + lk16);
    }

    const int NS = K >> 5;                 // 32-float stages

    auto issue = [&](int s, int b) {
        const float* as = Ap + (size_t)s * 32;
        const float* ws = Wp + (size_t)s * 32;
        #pragma unroll
        for (int i = 0; i < 4; ++i) {
            CP_ASYNC16(sAw[b] + i * 16, as + i * 4);
            CP_ASYNC16(sBw[b] + i * 16, ws + i * 4);
        }
    };

    issue(0, 0); CP_COMMIT();
    issue(1, 1); CP_COMMIT();

    float acc[4][4][4];
    #pragma unroll
    for (int i = 0; i < 4; i++)
        #pragma unroll
        for (int j = 0; j < 4; j++)
            #pragma unroll
            for (int r = 0; r < 4; r++) acc[i][j][r] = 0.f;

    for (int s = 0; s < NS; ++s) {
        CP_WAIT(1);                        // group for stage s complete
        __syncthreads();                   // all threads' data visible

        const int pb = s % GSTG;
        const float* Ab = gsm + (2 * pb    ) * GTILE;
        const float* Bb = gsm + (2 * pb + 1) * GTILE;

        #pragma unroll
        for (int ks = 0; ks < 4; ++ks) {
            const int kb = ks * 8;
            uint32_t af[4][4], bf[4][2];
            #pragma unroll
            for (int mt = 0; mt < 4; ++mt) {
                const int r = wm + mt * 16 + grp;
                af[mt][0] = __float_as_uint(Ab[(r    ) * GPAD + kb + qd]);
                af[mt][1] = __float_as_uint(Ab[(r + 8) * GPAD + kb + qd]);
                af[mt][2] = __float_as_uint(Ab[(r    ) * GPAD + kb + qd + 4]);
                af[mt][3] = __float_as_uint(Ab[(r + 8) * GPAD + kb + qd + 4]);
            }
            #pragma unroll
            for (int nt = 0; nt < 4; ++nt) {
                const int n = wn + nt * 8 + grp;
                bf[nt][0] = __float_as_uint(Bb[n * GPAD + kb + qd]);
                bf[nt][1] = __float_as_uint(Bb[n * GPAD + kb + qd + 4]);
            }
            #pragma unroll
            for (int mt = 0; mt < 4; ++mt)
                #pragma unroll
                for (int nt = 0; nt < 4; ++nt)
                    MMA_TF32(acc[mt][nt], af[mt], bf[nt]);
        }

        if (s + 2 < NS) issue(s + 2, (s + 2) % GSTG);
        CP_COMMIT();                       // unconditional: keeps group numbering
    }

    // epilogue: truncation-bias compensation + bias (+ReLU)
    const float COMP = 1.000704f;
    #pragma unroll
    for (int mt = 0; mt < 4; ++mt) {
        const int row = bm + wm + mt * 16 + grp;
        #pragma unroll
        for (int nt = 0; nt < 4; ++nt) {
            const int col = bn + wn + nt * 8 + 2 * qd;
            const float2 bv = *(const float2*)&bias[col];
            float2 o0, o1;
            o0.x = fmaf(acc[mt][nt][0], COMP, bv.x);
            o0.y = fmaf(acc[mt][nt][1], COMP, bv.y);
            o1.x = fmaf(acc[mt][nt][2], COMP, bv.x);
            o1.y = fmaf(acc[mt][nt][3], COMP, bv.y);
            if (RELU) {
                o0.x = fmaxf(o0.x, 0.f); o0.y = fmaxf(o0.y, 0.f);
                o1.x = fmaxf(o1.x, 0.f); o1.y = fmaxf(o1.y, 0.f);
            }
            *(float2*)(C + (size_t)row * N + col)       = o0;
            *(float2*)(C + (size_t)(row + 8) * N + col) = o1;
        }
    }
}

// ---------------------------------------------------------------------------
// mask tile flags (unchanged).
// ---------------------------------------------------------------------------
__global__ __launch_bounds__(256)
void mask_flags(const int* __restrict__ mask, int* __restrict__ flags)
{
    const int idx = blockIdx.x;
    const int qt = idx >> 5, st = idx & 31;
    const int tid = threadIdx.x;
    int ok = 1;
    for (int i = tid; i < 128 * 64; i += 256) {
        int r = qt * 128 + (i >> 6);
        int c = st * 64 + (i & 63);
        ok &= (mask[(size_t)r * LL + c] != 0);
    }
    int all = __syncthreads_and(ok);
    if (tid == 0) flags[idx] = all;
}

// ---------------------------------------------------------------------------
// Flash attention (R7-exact — proven).
// ---------------------------------------------------------------------------
#define AST 72
#define ATT_SMEM ((128 * AST + 64 * AST + 64 * AST) * 4)   // 73728 B

__global__ __launch_bounds__(256)
void flash_attn_mma(const float* __restrict__ qkv, const int* __restrict__ mask,
                    const int* __restrict__ flags, float* __restrict__ vals)
{
    extern __shared__ float sm[];
    float* Qs = sm;                        // [128][AST], k-interleaved, scaled
    float* Ks = sm + 128 * AST;            // [64][AST],  k-interleaved
    float* Vs = Ks + 64 * AST;             // [64][AST],  normal layout

    const int tid  = threadIdx.x;
    const int wid  = tid >> 5, lane = tid & 31;
    const int grp  = lane >> 2, qd = lane & 3;
    const int qt   = blockIdx.x;
    const int head = blockIdx.y;
    const int b    = blockIdx.z;
    const int qbase = qt * 128;
    const int m0   = wid * 16;

    const float QSCALE = 0.125f * 1.44269504088896340736f;   // (1/8)*log2(e)

    const float* qp = qkv + ((size_t)(b * LL + qbase)) * (3 * DD) + head * (3 * HD);
    for (int s = tid; s < 128 * 16; s += 256) {
        int r = s >> 4, c = (s & 15) * 4;
        float4 v = *(const float4*)(qp + (size_t)r * (3 * DD) + c);
        const int kb = c & ~7, h = (c >> 2) & 1;
        uint32_t* row = (uint32_t*)&Qs[r * AST + kb + h];
        row[0] = f2tf32(v.x * QSCALE); row[2] = f2tf32(v.y * QSCALE);
        row[4] = f2tf32(v.z * QSCALE); row[6] = f2tf32(v.w * QSCALE);
    }

    float o[8][4];
    #pragma unroll
    for (int nt = 0; nt < 8; ++nt)
        #pragma unroll
        for (int r = 0; r < 4; ++r) o[nt][r] = 0.f;
    float m_0 = -INFINITY, m_1 = -INFINITY, l_0 = 0.f, l_1 = 0.f;

    for (int st = 0; st < LL / 64; ++st) {
        __syncthreads();
        const int sbase = st * 64;
        const float* kp = qkv + ((size_t)(b * LL + sbase)) * (3 * DD) + head * (3 * HD) + HD;
        for (int s = tid; s < 64 * 16; s += 256) {
            int r = s >> 4, c = (s & 15) * 4;
            float4 kv = *(const float4*)(kp + (size_t)r * (3 * DD) + c);
            float4 vv = *(const float4*)(kp + (size_t)r * (3 * DD) + HD + c);
            const int kb = c & ~7, h = (c >> 2) & 1;
            uint32_t* krow = (uint32_t*)&Ks[r * AST + kb + h];
            krow[0] = f2tf32(kv.x); krow[2] = f2tf32(kv.y);
            krow[4] = f2tf32(kv.z); krow[6] = f2tf32(kv.w);
            uint32_t* vrow = (uint32_t*)&Vs[r * AST + c];
            vrow[0] = f2tf32(vv.x); vrow[1] = f2tf32(vv.y);
            vrow[2] = f2tf32(vv.z); vrow[3] = f2tf32(vv.w);
        }
        __syncthreads();

        float sacc[8][4];
        #pragma unroll
        for (int nt = 0; nt < 8; ++nt)
            #pragma unroll
            for (int r = 0; r < 4; ++r) sacc[nt][r] = 0.f;

        #pragma unroll
        for (int ks = 0; ks < 8; ++ks) {
            const int k0 = ks * 8;
            uint32_t a[4];
            {
                uint2 a02 = *(const uint2*)&Qs[(m0 + grp    ) * AST + k0 + 2 * qd];
                uint2 a13 = *(const uint2*)&Qs[(m0 + grp + 8) * AST + k0 + 2 * qd];
                a[0] = a02.x; a[1] = a13.x; a[2] = a02.y; a[3] = a13.y;
            }
            #pragma unroll
            for (int nt = 0; nt < 8; ++nt) {
                uint2 b01 = *(const uint2*)&Ks[(nt * 8 + grp) * AST + k0 + 2 * qd];
                uint32_t bb[2] = { b01.x, b01.y };
                MMA_TF32(sacc[nt], a, bb);
            }
        }

        if (flags[qt * 32 + st] == 0) {
            const int r0g = qbase + m0 + grp, r1g = r0g + 8;
            #pragma unroll
            for (int nt = 0; nt < 8; ++nt) {
                const int c0 = sbase + nt * 8 + 2 * qd;
                if (mask[(size_t)r0g * LL + c0    ] == 0) sacc[nt][0] = -INFINITY;
                if (mask[(size_t)r0g * LL + c0 + 1] == 0) sacc[nt][1] = -INFINITY;
                if (mask[(size_t)r1g * LL + c0    ] == 0) sacc[nt][2] = -INFINITY;
                if (mask[(size_t)r1g * LL + c0 + 1] == 0) sacc[nt][3] = -INFINITY;
            }
        }

        float rm0 = -INFINITY, rm1 = -INFINITY;
        #pragma unroll
        for (int nt = 0; nt < 8; ++nt) {
            rm0 = fmaxf(rm0, fmaxf(sacc[nt][0], sacc[nt][1]));
            rm1 = fmaxf(rm1, fmaxf(sacc[nt][2], sacc[nt][3]));
        }
        rm0 = fmaxf(rm0, __shfl_xor_sync(0xffffffffu, rm0, 1));
        rm0 = fmaxf(rm0, __shfl_xor_sync(0xffffffffu, rm0, 2));
        rm1 = fmaxf(rm1, __shfl_xor_sync(0xffffffffu, rm1, 1));
        rm1 = fmaxf(rm1, __shfl_xor_sync(0xffffffffu, rm1, 2));
        const float mn0 = fmaxf(m_0, rm0), mn1 = fmaxf(m_1, rm1);
        const float al0 = exp2f(m_0 - mn0), al1 = exp2f(m_1 - mn1);
        m_0 = mn0; m_1 = mn1;

        float s0 = 0.f, s1 = 0.f;
        #pragma unroll
        for (int nt = 0; nt < 8; ++nt) {
            float p0 = __uint_as_float(f2tf32(exp2f(sacc[nt][0] - mn0)));
            float p1 = __uint_as_float(f2tf32(exp2f(sacc[nt][1] - mn0)));
            float p2 = __uint_as_float(f2tf32(exp2f(sacc[nt][2] - mn1)));
            float p3 = __uint_as_float(f2tf32(exp2f(sacc[nt][3] - mn1)));
            sacc[nt][0] = p0; sacc[nt][1] = p1; sacc[nt][2] = p2; sacc[nt][3] = p3;
            s0 += p0 + p1; s1 += p2 + p3;
        }
        s0 += __shfl_xor_sync(0xffffffffu, s0, 1);
        s0 += __shfl_xor_sync(0xffffffffu, s0, 2);
        s1 += __shfl_xor_sync(0xffffffffu, s1, 1);
        s1 += __shfl_xor_sync(0xffffffffu, s1, 2);
        l_0 = l_0 * al0 + s0;
        l_1 = l_1 * al1 + s1;
        #pragma unroll
        for (int nt = 0; nt < 8; ++nt) {
            o[nt][0] *= al0; o[nt][1] *= al0;
            o[nt][2] *= al1; o[nt][3] *= al1;
        }

        const int srl = (lane & ~3) | (qd >> 1);
        #pragma unroll
        for (int ks = 0; ks < 8; ++ks) {
            uint32_t a[4];
            {
                float t0 = __shfl_sync(0xffffffffu, sacc[ks][0], srl);
                float t1 = __shfl_sync(0xffffffffu, sacc[ks][1], srl);
                float u0 = __shfl_sync(0xffffffffu, sacc[ks][0], srl + 2);
                float u1 = __shfl_sync(0xffffffffu, sacc[ks][1], srl + 2);
                a[0] = __float_as_uint((qd & 1) ? t1 : t0);
                a[2] = __float_as_uint((qd & 1) ? u1 : u0);
                t0 = __shfl_sync(0xffffffffu, sacc[ks][2], srl);
                t1 = __shfl_sync(0xffffffffu, sacc[ks][3], srl);
                u0 = __shfl_sync(0xffffffffu, sacc[ks][2], srl + 2);
                u1 = __shfl_sync(0xffffffffu, sacc[ks][3], srl + 2);
                a[1] = __float_as_uint((qd & 1) ? t1 : t0);
                a[3] = __float_as_uint((qd & 1) ? u1 : u0);
            }
            const int k0 = ks * 8;
            #pragma unroll
            for (int nt = 0; nt < 8; ++nt) {
                uint32_t bb[2];
                bb[0] = __float_as_uint(Vs[(k0 + qd    ) * AST + nt * 8 + grp]);
                bb[1] = __float_as_uint(Vs[(k0 + qd + 4) * AST + nt * 8 + grp]);
                MMA_TF32(o[nt], a, bb);
            }
        }
    }

    const float li0 = 1.f / l_0, li1 = 1.f / l_1;
    const int r0g = qbase + m0 + grp;
    #pragma unroll
    for (int nt = 0; nt < 8; ++nt) {
        const int col = head * HD + nt * 8 + 2 * qd;
        float2 w0 = make_float2(o[nt][0] * li0, o[nt][1] * li0);
        float2 w1 = make_float2(o[nt][2] * li1, o[nt][3] * li1);
        *(float2*)&vals[((size_t)(b * LL + r0g    )) * DD + col] = w0;
        *(float2*)&vals[((size_t)(b * LL + r0g + 8)) * DD + col] = w1;
    }
}

// ---------------------------------------------------------------------------
// Fused residual-add + LayerNorm (unchanged).
// ---------------------------------------------------------------------------
__global__ __launch_bounds__(128)
void add_ln(const float* __restrict__ a, const float* __restrict__ bres,
            const float* __restrict__ g, const float* __restrict__ beta,
            float* __restrict__ out)
{
    const int row = blockIdx.x;
    const int tid = threadIdx.x;

    float4 av = ((const float4*)(a    + (size_t)row * DD))[tid];
    float4 bv = ((const float4*)(bres + (size_t)row * DD))[tid];
    float4 x = make_float4(av.x+bv.x, av.y+bv.y, av.z+bv.z, av.w+bv.w);

    float s  = x.x + x.y + x.z + x.w;
    float ss = x.x*x.x + x.y*x.y + x.z*x.z + x.w*x.w;

    #pragma unroll
    for (int o = 16; o > 0; o >>= 1) {
        s  += __shfl_xor_sync(0xffffffffu, s,  o);
        ss += __shfl_xor_sync(0xffffffffu, ss, o);
    }
    __shared__ float red[2][4];
    const int w = tid >> 5, l = tid & 31;
    if (l == 0) { red[0][w] = s; red[1][w] = ss; }
    __syncthreads();
    s  = red[0][0] + red[0][1] + red[0][2] + red[0][3];
    ss = red[1][0] + red[1][1] + red[1][2] + red[1][3];

    const float mean = s * (1.f / DD);
    const float var  = ss * (1.f / DD) - mean * mean;
    const float rstd = rsqrtf(var + 1e-5f);

    float4 gv = ((const float4*)g)[tid];
    float4 ev = ((const float4*)beta)[tid];
    float4 o;
    o.x = (x.x - mean) * rstd * gv.x + ev.x;
    o.y = (x.y - mean) * rstd * gv.y + ev.y;
    o.z = (x.z - mean) * rstd * gv.z + ev.z;
    o.w = (x.w - mean) * rstd * gv.w + ev.w;
    ((float4*)(out + (size_t)row * DD))[tid] = o;
}

// ---------------------------------------------------------------------------
extern "C" void kernel_launch(void* const* d_in, const int* in_sizes, int n_in,
                              void* d_out, int out_size)
{
    const float* src    = (const float*)d_in[0];
    const int*   mask   = (const int*)  d_in[1];
    const float* qkv_w  = (const float*)d_in[2];
    const float* qkv_b  = (const float*)d_in[3];
    const float* out_w  = (const float*)d_in[4];
    const float* out_b  = (const float*)d_in[5];
    const float* w1     = (const float*)d_in[6];
    const float* b1     = (const float*)d_in[7];
    const float* w2     = (const float*)d_in[8];
    const float* b2     = (const float*)d_in[9];
    const float* g1     = (const float*)d_in[10];
    const float* beta1  = (const float*)d_in[11];
    const float* g2     = (const float*)d_in[12];
    const float* beta2  = (const float*)d_in[13];
    float* out = (float*)d_out;

    void* p;
    cudaGetSymbolAddress(&p, g_qkv);   float* qkv   = (float*)p;
    cudaGetSymbolAddress(&p, g_vals);  float* vals  = (float*)p;
    cudaGetSymbolAddress(&p, g_tmp);   float* tmp   = (float*)p;
    cudaGetSymbolAddress(&p, g_x1);    float* x1    = (float*)p;
    cudaGetSymbolAddress(&p, g_ff);    float* ff    = (float*)p;
    cudaGetSymbolAddress(&p, g_mflag); int*   mflag = (int*)p;

    cudaFuncSetAttribute(mma_gemm<0>, cudaFuncAttributeMaxDynamicSharedMemorySize, GEMM_SMEM);
    cudaFuncSetAttribute(mma_gemm<1>, cudaFuncAttributeMaxDynamicSharedMemorySize, GEMM_SMEM);
    cudaFuncSetAttribute(flash_attn_mma, cudaFuncAttributeMaxDynamicSharedMemorySize, ATT_SMEM);

    // 0) mask tile flags
    mask_flags<<<512, 256>>>(mask, mflag);

    // 1) QKV projection
    mma_gemm<0><<<dim3((3*DD)/128, MR/128), 256, GEMM_SMEM>>>(src, qkv_w, qkv_b, qkv, MR, 3*DD, DD);

    // 2) flash attention
    flash_attn_mma<<<dim3(LL/128, HH, BB), 256, ATT_SMEM>>>(qkv, mask, mflag, vals);

    // 3) output projection
    mma_gemm<0><<<dim3(DD/128, MR/128), 256, GEMM_SMEM>>>(vals, out_w, out_b, tmp, MR, DD, DD);

    // 4) x1 = LN(src + proj)
    add_ln<<<MR, 128>>>(src, tmp, g1, beta1, x1);

    // 5) FFN1 + ReLU
    mma_gemm<1><<<dim3(DFF/128, MR/128), 256, GEMM_SMEM>>>(x1, w1, b1, ff, MR, DFF, DD);

    // 6) FFN2
    mma_gemm<0><<<dim3(DD/128, MR/128), 256, GEMM_SMEM>>>(ff, w2, b2, tmp, MR, DD, DFF);

    // 7) out = LN(x1 + ffn2)
    add_ln<<<MR, 128>>>(x1, tmp, g2, beta2, out);
}

// round 13
// speedup vs baseline: 1.3610x; 1.3610x over previous
#include <cuda_runtime.h>
#include <cuda_fp16.h>
#include <math.h>
#include <stdint.h>

// Problem constants
#define BB   4
#define LL   2048
#define DD   512
#define HH   8
#define HD   64
#define DFF  2048
#define MR   (BB*LL)   // 8192 rows

// ---------------- scratch (device globals: allocation-free) ----------------
__device__ float  g_qkv [MR * 3 * DD];
__device__ float  g_tmp [MR * DD];
__device__ float  g_x1  [MR * DD];
__device__ int    g_mflag[16 * 32];
// fp16 operand copies
__device__ __half h_src [MR * DD];
__device__ __half h_qkvw[3 * DD * DD];
__device__ __half h_outw[DD * DD];
__device__ __half h_w1  [DFF * DD];
__device__ __half h_w2  [DD * DFF];
__device__ __half h_vals[MR * DD];
__device__ __half h_x1  [MR * DD];
__device__ __half h_ff  [MR * DFF];

// ---------------------------------------------------------------------------
// helpers
// ---------------------------------------------------------------------------
__device__ __forceinline__ uint32_t f2tf32(float x) {
    uint32_t r;
    asm("cvt.rna.tf32.f32 %0, %1;" : "=r"(r) : "f"(x));
    return r;
}
__device__ __forceinline__ uint32_t smem_u32(const void* p) {
    uint32_t a;
    asm("{ .reg .u64 t; cvta.to.shared.u64 t, %1; cvt.u32.u64 %0, t; }"
        : "=r"(a) : "l"(p));
    return a;
}

#define MMA_TF32(d, a, b)                                                      \
    asm volatile("mma.sync.aligned.m16n8k8.row.col.f32.tf32.tf32.f32 "         \
        "{%0,%1,%2,%3}, {%4,%5,%6,%7}, {%8,%9}, {%0,%1,%2,%3};"                \
        : "+f"((d)[0]), "+f"((d)[1]), "+f"((d)[2]), "+f"((d)[3])               \
        : "r"((a)[0]), "r"((a)[1]), "r"((a)[2]), "r"((a)[3]),                  \
          "r"((b)[0]), "r"((b)[1]))

#define MMA_F16(d, a, b)                                                       \
    asm volatile("mma.sync.aligned.m16n8k16.row.col.f32.f16.f16.f32 "          \
        "{%0,%1,%2,%3}, {%4,%5,%6,%7}, {%8,%9}, {%0,%1,%2,%3};"                \
        : "+f"((d)[0]), "+f"((d)[1]), "+f"((d)[2]), "+f"((d)[3])               \
        : "r"((a)[0]), "r"((a)[1]), "r"((a)[2]), "r"((a)[3]),                  \
          "r"((b)[0]), "r"((b)[1]))

#define CP_ASYNC16(dst, src)                                                   \
    asm volatile("cp.async.cg.shared.global [%0], [%1], 16;"                   \
        :: "r"(dst), "l"(src) : "memory")
#define CP_COMMIT() asm volatile("cp.async.commit_group;" ::: "memory")
#define CP_WAIT(n)  asm volatile("cp.async.wait_group %0;" :: "n"(n) : "memory")

// ---------------------------------------------------------------------------
// fp32 -> fp16 conversion (vectorized)
// ---------------------------------------------------------------------------
__global__ __launch_bounds__(256)
void f2h(const float* __restrict__ in, __half* __restrict__ out, int n)
{
    int i = (blockIdx.x * 256 + threadIdx.x) * 4;
    const int stride = gridDim.x * 256 * 4;
    for (; i < n; i += stride) {
        float4 v = *(const float4*)(in + i);
        __half2 h0 = __floats2half2_rn(v.x, v.y);
        __half2 h1 = __floats2half2_rn(v.z, v.w);
        *(__half2*)(out + i)     = h0;
        *(__half2*)(out + i + 2) = h1;
    }
}

// ---------------------------------------------------------------------------
// fp16 mma.sync GEMM v4: m16n8k16, BK=32 halfs/stage, 3-stage cp.async.
// 2x K per MMA instruction vs tf32 -> tensor time halves.
// GPAD=40 halfs (80B stride): fragment banks (20*grp+qd)(+4) mod 32 distinct.
// OUTH=1 writes fp16-only C; else fp32 C.
// ---------------------------------------------------------------------------
#define GPAD 40                             // halfs per smem row
#define GTILE (128 * GPAD)                  // halfs per tensor per stage
#define GSTG 3
#define GEMM_SMEM (GSTG * 2 * GTILE * 2)    // 61440 bytes

template<int RELU, int OUTH>
__global__ __launch_bounds__(256, 2)
void mma_gemm(const __half* __restrict__ A, const __half* __restrict__ W,
              const float* __restrict__ bias, float* __restrict__ C,
              __half* __restrict__ CH, int M, int N, int K)
{
    extern __shared__ __half gsm[];

    const int tid  = threadIdx.x;
    const int wid  = tid >> 5, lane = tid & 31;
    const int grp  = lane >> 2, qd = lane & 3;
    const int wm   = (wid & 1) * 64;
    const int wn   = (wid >> 1) * 32;
    const int bm   = blockIdx.y * 128;
    const int bn   = blockIdx.x * 128;

    const int lrow = tid >> 1;              // 0..127
    const int lk16 = (tid & 1) * 16;        // 0 or 16 halfs

    const __half* Ap = A + (size_t)(bm + lrow) * K + lk16;
    const __half* Wp = W + (size_t)(bn + lrow) * K + lk16;

    uint32_t sAw[GSTG], sBw[GSTG];
    #pragma unroll
    for (int b = 0; b < GSTG; ++b) {
        sAw[b] = smem_u32(gsm + (2 * b    ) * GTILE + lrow * GPAD + lk16);
        sBw[b] = smem_u32(gsm + (2 * b + 1) * GTILE + lrow * GPAD + lk16);
    }

    const int NS = K >> 5;                  // 32-half stages

    auto issue = [&](int s, int b) {
        const __half* as = Ap + (size_t)s * 32;
        const __half* ws = Wp + (size_t)s * 32;
        CP_ASYNC16(sAw[b],      as);
        CP_ASYNC16(sAw[b] + 16, as + 8);
        CP_ASYNC16(sBw[b],      ws);
        CP_ASYNC16(sBw[b] + 16, ws + 8);
    };

    issue(0, 0); CP_COMMIT();
    issue(1, 1); CP_COMMIT();

    float acc[4][4][4];
    #pragma unroll
    for (int i = 0; i < 4; i++)
        #pragma unroll
        for (int j = 0; j < 4; j++)
            #pragma unroll
            for (int r = 0; r < 4; r++) acc[i][j][r] = 0.f;

    for (int s = 0; s < NS; ++s) {
        CP_WAIT(1);
        __syncthreads();

        const int pb = s % GSTG;
        const __half* Ab = gsm + (2 * pb    ) * GTILE;
        const __half* Bb = gsm + (2 * pb + 1) * GTILE;

        #pragma unroll
        for (int ks = 0; ks < 2; ++ks) {    // 2 x K=16
            const int kb = ks * 16;
            uint32_t af[4][4], bf[4][2];
            #pragma unroll
            for (int mt = 0; mt < 4; ++mt) {
                const int r = wm + mt * 16 + grp;
                af[mt][0] = *(const uint32_t*)&Ab[(r    ) * GPAD + kb + 2 * qd];
                af[mt][1] = *(const uint32_t*)&Ab[(r + 8) * GPAD + kb + 2 * qd];
                af[mt][2] = *(const uint32_t*)&Ab[(r    ) * GPAD + kb + 2 * qd + 8];
                af[mt][3] = *(const uint32_t*)&Ab[(r + 8) * GPAD + kb + 2 * qd + 8];
            }
            #pragma unroll
            for (int nt = 0; nt < 4; ++nt) {
                const int n = wn + nt * 8 + grp;
                bf[nt][0] = *(const uint32_t*)&Bb[n * GPAD + kb + 2 * qd];
                bf[nt][1] = *(const uint32_t*)&Bb[n * GPAD + kb + 2 * qd + 8];
            }
            #pragma unroll
            for (int mt = 0; mt < 4; ++mt)
                #pragma unroll
                for (int nt = 0; nt < 4; ++nt)
                    MMA_F16(acc[mt][nt], af[mt], bf[nt]);
        }

        if (s + 2 < NS) issue(s + 2, (s + 2) % GSTG);
        CP_COMMIT();
    }

    // epilogue: + bias (+ReLU); fp32 or fp16 output
    #pragma unroll
    for (int mt = 0; mt < 4; ++mt) {
        const int row = bm + wm + mt * 16 + grp;
        #pragma unroll
        for (int nt = 0; nt < 4; ++nt) {
            const int col = bn + wn + nt * 8 + 2 * qd;
            const float2 bv = *(const float2*)&bias[col];
            float2 o0, o1;
            o0.x = acc[mt][nt][0] + bv.x; o0.y = acc[mt][nt][1] + bv.y;
            o1.x = acc[mt][nt][2] + bv.x; o1.y = acc[mt][nt][3] + bv.y;
            if (RELU) {
                o0.x = fmaxf(o0.x, 0.f); o0.y = fmaxf(o0.y, 0.f);
                o1.x = fmaxf(o1.x, 0.f); o1.y = fmaxf(o1.y, 0.f);
            }
            if (OUTH) {
                *(__half2*)(CH + (size_t)row * N + col)       = __floats2half2_rn(o0.x, o0.y);
                *(__half2*)(CH + (size_t)(row + 8) * N + col) = __floats2half2_rn(o1.x, o1.y);
            } else {
                *(float2*)(C + (size_t)row * N + col)       = o0;
                *(float2*)(C + (size_t)(row + 8) * N + col) = o1;
            }
        }
    }
}

// ---------------------------------------------------------------------------
// mask tile flags (unchanged).
// ---------------------------------------------------------------------------
__global__ __launch_bounds__(256)
void mask_flags(const int* __restrict__ mask, int* __restrict__ flags)
{
    const int idx = blockIdx.x;
    const int qt = idx >> 5, st = idx & 31;
    const int tid = threadIdx.x;
    int ok = 1;
    for (int i = tid; i < 128 * 64; i += 256) {
        int r = qt * 128 + (i >> 6);
        int c = st * 64 + (i & 63);
        ok &= (mask[(size_t)r * LL + c] != 0);
    }
    int all = __syncthreads_and(ok);
    if (tid == 0) flags[idx] = all;
}

// ---------------------------------------------------------------------------
// Flash attention (R7-exact body) — epilogue now writes fp16 h_vals.
// ---------------------------------------------------------------------------
#define AST 72
#define ATT_SMEM ((128 * AST + 64 * AST + 64 * AST) * 4)   // 73728 B

__global__ __launch_bounds__(256)
void flash_attn_mma(const float* __restrict__ qkv, const int* __restrict__ mask,
                    const int* __restrict__ flags, __half* __restrict__ hvals)
{
    extern __shared__ float sm[];
    float* Qs = sm;
    float* Ks = sm + 128 * AST;
    float* Vs = Ks + 64 * AST;

    const int tid  = threadIdx.x;
    const int wid  = tid >> 5, lane = tid & 31;
    const int grp  = lane >> 2, qd = lane & 3;
    const int qt   = blockIdx.x;
    const int head = blockIdx.y;
    const int b    = blockIdx.z;
    const int qbase = qt * 128;
    const int m0   = wid * 16;

    const float QSCALE = 0.125f * 1.44269504088896340736f;

    const float* qp = qkv + ((size_t)(b * LL + qbase)) * (3 * DD) + head * (3 * HD);
    for (int s = tid; s < 128 * 16; s += 256) {
        int r = s >> 4, c = (s & 15) * 4;
        float4 v = *(const float4*)(qp + (size_t)r * (3 * DD) + c);
        const int kb = c & ~7, h = (c >> 2) & 1;
        uint32_t* row = (uint32_t*)&Qs[r * AST + kb + h];
        row[0] = f2tf32(v.x * QSCALE); row[2] = f2tf32(v.y * QSCALE);
        row[4] = f2tf32(v.z * QSCALE); row[6] = f2tf32(v.w * QSCALE);
    }

    float o[8][4];
    #pragma unroll
    for (int nt = 0; nt < 8; ++nt)
        #pragma unroll
        for (int r = 0; r < 4; ++r) o[nt][r] = 0.f;
    float m_0 = -INFINITY, m_1 = -INFINITY, l_0 = 0.f, l_1 = 0.f;

    for (int st = 0; st < LL / 64; ++st) {
        __syncthreads();
        const int sbase = st * 64;
        const float* kp = qkv + ((size_t)(b * LL + sbase)) * (3 * DD) + head * (3 * HD) + HD;
        for (int s = tid; s < 64 * 16; s += 256) {
            int r = s >> 4, c = (s & 15) * 4;
            float4 kv = *(const float4*)(kp + (size_t)r * (3 * DD) + c);
            float4 vv = *(const float4*)(kp + (size_t)r * (3 * DD) + HD + c);
            const int kb = c & ~7, h = (c >> 2) & 1;
            uint32_t* krow = (uint32_t*)&Ks[r * AST + kb + h];
            krow[0] = f2tf32(kv.x); krow[2] = f2tf32(kv.y);
            krow[4] = f2tf32(kv.z); krow[6] = f2tf32(kv.w);
            uint32_t* vrow = (uint32_t*)&Vs[r * AST + c];
            vrow[0] = f2tf32(vv.x); vrow[1] = f2tf32(vv.y);
            vrow[2] = f2tf32(vv.z); vrow[3] = f2tf32(vv.w);
        }
        __syncthreads();

        float sacc[8][4];
        #pragma unroll
        for (int nt = 0; nt < 8; ++nt)
            #pragma unroll
            for (int r = 0; r < 4; ++r) sacc[nt][r] = 0.f;

        #pragma unroll
        for (int ks = 0; ks < 8; ++ks) {
            const int k0 = ks * 8;
            uint32_t a[4];
            {
                uint2 a02 = *(const uint2*)&Qs[(m0 + grp    ) * AST + k0 + 2 * qd];
                uint2 a13 = *(const uint2*)&Qs[(m0 + grp + 8) * AST + k0 + 2 * qd];
                a[0] = a02.x; a[1] = a13.x; a[2] = a02.y; a[3] = a13.y;
            }
            #pragma unroll
            for (int nt = 0; nt < 8; ++nt) {
                uint2 b01 = *(const uint2*)&Ks[(nt * 8 + grp) * AST + k0 + 2 * qd];
                uint32_t bb[2] = { b01.x, b01.y };
                MMA_TF32(sacc[nt], a, bb);
            }
        }

        if (flags[qt * 32 + st] == 0) {
            const int r0g = qbase + m0 + grp, r1g = r0g + 8;
            #pragma unroll
            for (int nt = 0; nt < 8; ++nt) {
                const int c0 = sbase + nt * 8 + 2 * qd;
                if (mask[(size_t)r0g * LL + c0    ] == 0) sacc[nt][0] = -INFINITY;
                if (mask[(size_t)r0g * LL + c0 + 1] == 0) sacc[nt][1] = -INFINITY;
                if (mask[(size_t)r1g * LL + c0    ] == 0) sacc[nt][2] = -INFINITY;
                if (mask[(size_t)r1g * LL + c0 + 1] == 0) sacc[nt][3] = -INFINITY;
            }
        }

        float rm0 = -INFINITY, rm1 = -INFINITY;
        #pragma unroll
        for (int nt = 0; nt < 8; ++nt) {
            rm0 = fmaxf(rm0, fmaxf(sacc[nt][0], sacc[nt][1]));
            rm1 = fmaxf(rm1, fmaxf(sacc[nt][2], sacc[nt][3]));
        }
        rm0 = fmaxf(rm0, __shfl_xor_sync(0xffffffffu, rm0, 1));
        rm0 = fmaxf(rm0, __shfl_xor_sync(0xffffffffu, rm0, 2));
        rm1 = fmaxf(rm1, __shfl_xor_sync(0xffffffffu, rm1, 1));
        rm1 = fmaxf(rm1, __shfl_xor_sync(0xffffffffu, rm1, 2));
        const float mn0 = fmaxf(m_0, rm0), mn1 = fmaxf(m_1, rm1);
        const float al0 = exp2f(m_0 - mn0), al1 = exp2f(m_1 - mn1);
        m_0 = mn0; m_1 = mn1;

        float s0 = 0.f, s1 = 0.f;
        #pragma unroll
        for (int nt = 0; nt < 8; ++nt) {
            float p0 = __uint_as_float(f2tf32(exp2f(sacc[nt][0] - mn0)));
            float p1 = __uint_as_float(f2tf32(exp2f(sacc[nt][1] - mn0)));
            float p2 = __uint_as_float(f2tf32(exp2f(sacc[nt][2] - mn1)));
            float p3 = __uint_as_float(f2tf32(exp2f(sacc[nt][3] - mn1)));
            sacc[nt][0] = p0; sacc[nt][1] = p1; sacc[nt][2] = p2; sacc[nt][3] = p3;
            s0 += p0 + p1; s1 += p2 + p3;
        }
        s0 += __shfl_xor_sync(0xffffffffu, s0, 1);
        s0 += __shfl_xor_sync(0xffffffffu, s0, 2);
        s1 += __shfl_xor_sync(0xffffffffu, s1, 1);
        s1 += __shfl_xor_sync(0xffffffffu, s1, 2);
        l_0 = l_0 * al0 + s0;
        l_1 = l_1 * al1 + s1;
        #pragma unroll
        for (int nt = 0; nt < 8; ++nt) {
            o[nt][0] *= al0; o[nt][1] *= al0;
            o[nt][2] *= al1; o[nt][3] *= al1;
        }

        const int srl = (lane & ~3) | (qd >> 1);
        #pragma unroll
        for (int ks = 0; ks < 8; ++ks) {
            uint32_t a[4];
            {
                float t0 = __shfl_sync(0xffffffffu, sacc[ks][0], srl);
                float t1 = __shfl_sync(0xffffffffu, sacc[ks][1], srl);
                float u0 = __shfl_sync(0xffffffffu, sacc[ks][0], srl + 2);
                float u1 = __shfl_sync(0xffffffffu, sacc[ks][1], srl + 2);
                a[0] = __float_as_uint((qd & 1) ? t1 : t0);
                a[2] = __float_as_uint((qd & 1) ? u1 : u0);
                t0 = __shfl_sync(0xffffffffu, sacc[ks][2], srl);
                t1 = __shfl_sync(0xffffffffu, sacc[ks][3], srl);
                u0 = __shfl_sync(0xffffffffu, sacc[ks][2], srl + 2);
                u1 = __shfl_sync(0xffffffffu, sacc[ks][3], srl + 2);
                a[1] = __float_as_uint((qd & 1) ? t1 : t0);
                a[3] = __float_as_uint((qd & 1) ? u1 : u0);
            }
            const int k0 = ks * 8;
            #pragma unroll
            for (int nt = 0; nt < 8; ++nt) {
                uint32_t bb[2];
                bb[0] = __float_as_uint(Vs[(k0 + qd    ) * AST + nt * 8 + grp]);
                bb[1] = __float_as_uint(Vs[(k0 + qd + 4) * AST + nt * 8 + grp]);
                MMA_TF32(o[nt], a, bb);
            }
        }
    }

    // normalize + write fp16 (head-concat [B,L,D])
    const float li0 = 1.f / l_0, li1 = 1.f / l_1;
    const int r0g = qbase + m0 + grp;
    #pragma unroll
    for (int nt = 0; nt < 8; ++nt) {
        const int col = head * HD + nt * 8 + 2 * qd;
        *(__half2*)&hvals[((size_t)(b * LL + r0g    )) * DD + col] =
            __floats2half2_rn(o[nt][0] * li0, o[nt][1] * li0);
        *(__half2*)&hvals[((size_t)(b * LL + r0g + 8)) * DD + col] =
            __floats2half2_rn(o[nt][2] * li1, o[nt][3] * li1);
    }
}

// ---------------------------------------------------------------------------
// Fused residual-add + LayerNorm; optional fp16 copy of the output.
// ---------------------------------------------------------------------------
template<int WH>
__global__ __launch_bounds__(128)
void add_ln(const float* __restrict__ a, const float* __restrict__ bres,
            const float* __restrict__ g, const float* __restrict__ beta,
            float* __restrict__ out, __half* __restrict__ hout)
{
    const int row = blockIdx.x;
    const int tid = threadIdx.x;

    float4 av = ((const float4*)(a    + (size_t)row * DD))[tid];
    float4 bv = ((const float4*)(bres + (size_t)row * DD))[tid];
    float4 x = make_float4(av.x+bv.x, av.y+bv.y, av.z+bv.z, av.w+bv.w);

    float s  = x.x + x.y + x.z + x.w;
    float ss = x.x*x.x + x.y*x.y + x.z*x.z + x.w*x.w;

    #pragma unroll
    for (int o = 16; o > 0; o >>= 1) {
        s  += __shfl_xor_sync(0xffffffffu, s,  o);
        ss += __shfl_xor_sync(0xffffffffu, ss, o);
    }
    __shared__ float red[2][4];
    const int w = tid >> 5, l = tid & 31;
    if (l == 0) { red[0][w] = s; red[1][w] = ss; }
    __syncthreads();
    s  = red[0][0] + red[0][1] + red[0][2] + red[0][3];
    ss = red[1][0] + red[1][1] + red[1][2] + red[1][3];

    const float mean = s * (1.f / DD);
    const float var  = ss * (1.f / DD) - mean * mean;
    const float rstd = rsqrtf(var + 1e-5f);

    float4 gv = ((const float4*)g)[tid];
    float4 ev = ((const float4*)beta)[tid];
    float4 o;
    o.x = (x.x - mean) * rstd * gv.x + ev.x;
    o.y = (x.y - mean) * rstd * gv.y + ev.y;
    o.z = (x.z - mean) * rstd * gv.z + ev.z;
    o.w = (x.w - mean) * rstd * gv.w + ev.w;
    ((float4*)(out + (size_t)row * DD))[tid] = o;
    if (WH) {
        *(__half2*)(hout + (size_t)row * DD + tid * 4)     = __floats2half2_rn(o.x, o.y);
        *(__half2*)(hout + (size_t)row * DD + tid * 4 + 2) = __floats2half2_rn(o.z, o.w);
    }
}

// ---------------------------------------------------------------------------
extern "C" void kernel_launch(void* const* d_in, const int* in_sizes, int n_in,
                              void* d_out, int out_size)
{
    const float* src    = (const float*)d_in[0];
    const int*   mask   = (const int*)  d_in[1];
    const float* qkv_w  = (const float*)d_in[2];
    const float* qkv_b  = (const float*)d_in[3];
    const float* out_w  = (const float*)d_in[4];
    const float* out_b  = (const float*)d_in[5];
    const float* w1     = (const float*)d_in[6];
    const float* b1     = (const float*)d_in[7];
    const float* w2     = (const float*)d_in[8];
    const float* b2     = (const float*)d_in[9];
    const float* g1     = (const float*)d_in[10];
    const float* beta1  = (const float*)d_in[11];
    const float* g2     = (const float*)d_in[12];
    const float* beta2  = (const float*)d_in[13];
    float* out = (float*)d_out;

    void* p;
    cudaGetSymbolAddress(&p, g_qkv);   float*  qkv   = (float*)p;
    cudaGetSymbolAddress(&p, g_tmp);   float*  tmp   = (float*)p;
    cudaGetSymbolAddress(&p, g_x1);    float*  x1    = (float*)p;
    cudaGetSymbolAddress(&p, g_mflag); int*    mflag = (int*)p;
    cudaGetSymbolAddress(&p, h_src);   __half* hsrc  = (__half*)p;
    cudaGetSymbolAddress(&p, h_qkvw);  __half* hqkvw = (__half*)p;
    cudaGetSymbolAddress(&p, h_outw);  __half* houtw = (__half*)p;
    cudaGetSymbolAddress(&p, h_w1);    __half* hw1   = (__half*)p;
    cudaGetSymbolAddress(&p, h_w2);    __half* hw2   = (__half*)p;
    cudaGetSymbolAddress(&p, h_vals);  __half* hvals = (__half*)p;
    cudaGetSymbolAddress(&p, h_x1);    __half* hx1   = (__half*)p;
    cudaGetSymbolAddress(&p, h_ff);    __half* hff   = (__half*)p;

    cudaFuncSetAttribute(mma_gemm<0,0>, cudaFuncAttributeMaxDynamicSharedMemorySize, GEMM_SMEM);
    cudaFuncSetAttribute(mma_gemm<1,1>, cudaFuncAttributeMaxDynamicSharedMemorySize, GEMM_SMEM);
    cudaFuncSetAttribute(flash_attn_mma, cudaFuncAttributeMaxDynamicSharedMemorySize, ATT_SMEM);

    // 0) operand conversions + mask flags
    f2h<<<256, 256>>>(src,   hsrc,  MR * DD);
    f2h<<<128, 256>>>(qkv_w, hqkvw, 3 * DD * DD);
    f2h<<<64,  256>>>(out_w, houtw, DD * DD);
    f2h<<<128, 256>>>(w1,    hw1,   DFF * DD);
    f2h<<<128, 256>>>(w2,    hw2,   DD * DFF);
    mask_flags<<<512, 256>>>(mask, mflag);

    // 1) QKV projection (fp16 in, fp32 out)
    mma_gemm<0,0><<<dim3((3*DD)/128, MR/128), 256, GEMM_SMEM>>>(
        hsrc, hqkvw, qkv_b, qkv, nullptr, MR, 3*DD, DD);

    // 2) flash attention -> h_vals (fp16)
    flash_attn_mma<<<dim3(LL/128, HH, BB), 256, ATT_SMEM>>>(qkv, mask, mflag, hvals);

    // 3) output projection (fp16 in, fp32 out)
    mma_gemm<0,0><<<dim3(DD/128, MR/128), 256, GEMM_SMEM>>>(
        hvals, houtw, out_b, tmp, nullptr, MR, DD, DD);

    // 4) x1 = LN(src + proj), also fp16 copy
    add_ln<1><<<MR, 128>>>(src, tmp, g1, beta1, x1, hx1);

    // 5) FFN1 + ReLU (fp16 in, fp16 out)
    mma_gemm<1,1><<<dim3(DFF/128, MR/128), 256, GEMM_SMEM>>>(
        hx1, hw1, b1, nullptr, hff, MR, DFF, DD);

    // 6) FFN2 (fp16 in, fp32 out)
    mma_gemm<0,0><<<dim3(DD/128, MR/128), 256, GEMM_SMEM>>>(
        hff, hw2, b2, tmp, nullptr, MR, DD, DFF);

    // 7) out = LN(x1 + ffn2)
    add_ln<0><<<MR, 128>>>(x1, tmp, g2, beta2, out, nullptr);
}

// round 15
// speedup vs baseline: 1.6693x; 1.2265x over previous
#include <cuda_runtime.h>
#include <cuda_fp16.h>
#include <math.h>
#include <stdint.h>

// Problem constants
#define BB   4
#define LL   2048
#define DD   512
#define HH   8
#define HD   64
#define DFF  2048
#define MR   (BB*LL)   // 8192 rows

// ---------------- scratch (device globals: allocation-free) ----------------
__device__ float  g_tmp [MR * DD];
__device__ float  g_x1  [MR * DD];
__device__ int    g_mflag[16 * 32];
__device__ __half h_qkv [MR * 3 * DD];
__device__ __half h_src [MR * DD];
__device__ __half h_qkvw[3 * DD * DD];
__device__ __half h_outw[DD * DD];
__device__ __half h_w1  [DFF * DD];
__device__ __half h_w2  [DD * DFF];
__device__ __half h_vals[MR * DD];
__device__ __half h_x1  [MR * DD];
__device__ __half h_ff  [MR * DFF];

// ---------------------------------------------------------------------------
// helpers
// ---------------------------------------------------------------------------
__device__ __forceinline__ uint32_t smem_u32(const void* p) {
    uint32_t a;
    asm("{ .reg .u64 t; cvta.to.shared.u64 t, %1; cvt.u32.u64 %0, t; }"
        : "=r"(a) : "l"(p));
    return a;
}

#define MMA_F16(d, a, b)                                                       \
    asm volatile("mma.sync.aligned.m16n8k16.row.col.f32.f16.f16.f32 "          \
        "{%0,%1,%2,%3}, {%4,%5,%6,%7}, {%8,%9}, {%0,%1,%2,%3};"                \
        : "+f"((d)[0]), "+f"((d)[1]), "+f"((d)[2]), "+f"((d)[3])               \
        : "r"((a)[0]), "r"((a)[1]), "r"((a)[2]), "r"((a)[3]),                  \
          "r"((b)[0]), "r"((b)[1]))

#define CP_ASYNC16(dst, src)                                                   \
    asm volatile("cp.async.cg.shared.global [%0], [%1], 16;"                   \
        :: "r"(dst), "l"(src) : "memory")
#define CP_COMMIT() asm volatile("cp.async.commit_group;" ::: "memory")
#define CP_WAIT(n)  asm volatile("cp.async.wait_group %0;" :: "n"(n) : "memory")

// ---------------------------------------------------------------------------
// fp32 -> fp16 conversion (vectorized)
// ---------------------------------------------------------------------------
__global__ __launch_bounds__(256)
void f2h(const float* __restrict__ in, __half* __restrict__ out, int n)
{
    int i = (blockIdx.x * 256 + threadIdx.x) * 4;
    const int stride = gridDim.x * 256 * 4;
    for (; i < n; i += stride) {
        float4 v = *(const float4*)(in + i);
        *(__half2*)(out + i)     = __floats2half2_rn(v.x, v.y);
        *(__half2*)(out + i + 2) = __floats2half2_rn(v.z, v.w);
    }
}

// ---------------------------------------------------------------------------
// fp16 mma.sync GEMM (R13-proven): m16n8k16, BK=32 halfs, 3-stage cp.async.
// ---------------------------------------------------------------------------
#define GPAD 40
#define GTILE (128 * GPAD)
#define GSTG 3
#define GEMM_SMEM (GSTG * 2 * GTILE * 2)    // 61440 bytes

template<int RELU, int OUTH>
__global__ __launch_bounds__(256, 2)
void mma_gemm(const __half* __restrict__ A, const __half* __restrict__ W,
              const float* __restrict__ bias, float* __restrict__ C,
              __half* __restrict__ CH, int M, int N, int K)
{
    extern __shared__ __half gsm[];

    const int tid  = threadIdx.x;
    const int wid  = tid >> 5, lane = tid & 31;
    const int grp  = lane >> 2, qd = lane & 3;
    const int wm   = (wid & 1) * 64;
    const int wn   = (wid >> 1) * 32;
    const int bm   = blockIdx.y * 128;
    const int bn   = blockIdx.x * 128;

    const int lrow = tid >> 1;
    const int lk16 = (tid & 1) * 16;

    const __half* Ap = A + (size_t)(bm + lrow) * K + lk16;
    const __half* Wp = W + (size_t)(bn + lrow) * K + lk16;

    uint32_t sAw[GSTG], sBw[GSTG];
    #pragma unroll
    for (int b = 0; b < GSTG; ++b) {
        sAw[b] = smem_u32(gsm + (2 * b    ) * GTILE + lrow * GPAD + lk16);
        sBw[b] = smem_u32(gsm + (2 * b + 1) * GTILE + lrow * GPAD + lk16);
    }

    const int NS = K >> 5;

    auto issue = [&](int s, int b) {
        const __half* as = Ap + (size_t)s * 32;
        const __half* ws = Wp + (size_t)s * 32;
        CP_ASYNC16(sAw[b],      as);
        CP_ASYNC16(sAw[b] + 16, as + 8);
        CP_ASYNC16(sBw[b],      ws);
        CP_ASYNC16(sBw[b] + 16, ws + 8);
    };

    issue(0, 0); CP_COMMIT();
    issue(1, 1); CP_COMMIT();

    float acc[4][4][4];
    #pragma unroll
    for (int i = 0; i < 4; i++)
        #pragma unroll
        for (int j = 0; j < 4; j++)
            #pragma unroll
            for (int r = 0; r < 4; r++) acc[i][j][r] = 0.f;

    for (int s = 0; s < NS; ++s) {
        CP_WAIT(1);
        __syncthreads();

        const int pb = s % GSTG;
        const __half* Ab = gsm + (2 * pb    ) * GTILE;
        const __half* Bb = gsm + (2 * pb + 1) * GTILE;

        #pragma unroll
        for (int ks = 0; ks < 2; ++ks) {
            const int kb = ks * 16;
            uint32_t af[4][4], bf[4][2];
            #pragma unroll
            for (int mt = 0; mt < 4; ++mt) {
                const int r = wm + mt * 16 + grp;
                af[mt][0] = *(const uint32_t*)&Ab[(r    ) * GPAD + kb + 2 * qd];
                af[mt][1] = *(const uint32_t*)&Ab[(r + 8) * GPAD + kb + 2 * qd];
                af[mt][2] = *(const uint32_t*)&Ab[(r    ) * GPAD + kb + 2 * qd + 8];
                af[mt][3] = *(const uint32_t*)&Ab[(r + 8) * GPAD + kb + 2 * qd + 8];
            }
            #pragma unroll
            for (int nt = 0; nt < 4; ++nt) {
                const int n = wn + nt * 8 + grp;
                bf[nt][0] = *(const uint32_t*)&Bb[n * GPAD + kb + 2 * qd];
                bf[nt][1] = *(const uint32_t*)&Bb[n * GPAD + kb + 2 * qd + 8];
            }
            #pragma unroll
            for (int mt = 0; mt < 4; ++mt)
                #pragma unroll
                for (int nt = 0; nt < 4; ++nt)
                    MMA_F16(acc[mt][nt], af[mt], bf[nt]);
        }

        if (s + 2 < NS) issue(s + 2, (s + 2) % GSTG);
        CP_COMMIT();
    }

    #pragma unroll
    for (int mt = 0; mt < 4; ++mt) {
        const int row = bm + wm + mt * 16 + grp;
        #pragma unroll
        for (int nt = 0; nt < 4; ++nt) {
            const int col = bn + wn + nt * 8 + 2 * qd;
            const float2 bv = *(const float2*)&bias[col];
            float2 o0, o1;
            o0.x = acc[mt][nt][0] + bv.x; o0.y = acc[mt][nt][1] + bv.y;
            o1.x = acc[mt][nt][2] + bv.x; o1.y = acc[mt][nt][3] + bv.y;
            if (RELU) {
                o0.x = fmaxf(o0.x, 0.f); o0.y = fmaxf(o0.y, 0.f);
                o1.x = fmaxf(o1.x, 0.f); o1.y = fmaxf(o1.y, 0.f);
            }
            if (OUTH) {
                *(__half2*)(CH + (size_t)row * N + col)       = __floats2half2_rn(o0.x, o0.y);
                *(__half2*)(CH + (size_t)(row + 8) * N + col) = __floats2half2_rn(o1.x, o1.y);
            } else {
                *(float2*)(C + (size_t)row * N + col)       = o0;
                *(float2*)(C + (size_t)(row + 8) * N + col) = o1;
            }
        }
    }
}

// ---------------------------------------------------------------------------
// mask tile flags (unchanged).
// ---------------------------------------------------------------------------
__global__ __launch_bounds__(256)
void mask_flags(const int* __restrict__ mask, int* __restrict__ flags)
{
    const int idx = blockIdx.x;
    const int qt = idx >> 5, st = idx & 31;
    const int tid = threadIdx.x;
    int ok = 1;
    for (int i = tid; i < 128 * 64; i += 256) {
        int r = qt * 128 + (i >> 6);
        int c = st * 64 + (i & 63);
        ok &= (mask[(size_t)r * LL + c] != 0);
    }
    int all = __syncthreads_and(ok);
    if (tid == 0) flags[idx] = all;
}

// ---------------------------------------------------------------------------
// Flash attention v3: fully fp16 mma (m16n8k16), fp16 QKV input.
// - QKT and PV at K=16/MMA: 32+32 MMAs per warp-tile (was 64+64).
// - PV A-frag == S C-frag layout -> shuffles eliminated; P packed via
//   __floats2half2_rn (p fp16-rounded BEFORE l-summation for consistency).
// - V stored row-pair-packed: Vp[s/2][c] = (V[s][c], V[s+1][c]) so PV B-frags
//   are single LDS.32. Strides: Q/K 72 halfs, Vp 72 words — conflict-free.
// - smem 36.9KB/CTA.
// ---------------------------------------------------------------------------
#define QSH 72                              // Q/K row stride in halfs
#define VPS 72                              // Vp row stride in words
#define ATT_SMEM ((128 * QSH + 64 * QSH) * 2 + 32 * VPS * 4)   // 36864 B

__global__ __launch_bounds__(256)
void flash_attn_mma(const __half* __restrict__ qkv, const int* __restrict__ mask,
                    const int* __restrict__ flags, __half* __restrict__ hvals)
{
    extern __shared__ char asm_raw[];
    __half*   Qs = (__half*)asm_raw;                      // [128][QSH]
    __half*   Ks = Qs + 128 * QSH;                        // [64][QSH]
    uint32_t* Vp = (uint32_t*)(Ks + 64 * QSH);            // [32][VPS]

    const int tid  = threadIdx.x;
    const int wid  = tid >> 5, lane = tid & 31;
    const int grp  = lane >> 2, qd = lane & 3;
    const int qt   = blockIdx.x;
    const int head = blockIdx.y;
    const int b    = blockIdx.z;
    const int qbase = qt * 128;
    const int m0   = wid * 16;

    const float QSCALE = 0.125f * 1.44269504088896340736f;   // (1/8)*log2(e)

    // ---- Q tile: fp16 in, scale, fp16 out ----
    const __half* qp = qkv + ((size_t)(b * LL + qbase)) * (3 * DD) + head * (3 * HD);
    for (int s = tid; s < 128 * 8; s += 256) {
        int r = s >> 3, c = (s & 7) * 8;
        const __half2* src2 = (const __half2*)(qp + (size_t)r * (3 * DD) + c);
        __half2* dst2 = (__half2*)&Qs[r * QSH + c];
        #pragma unroll
        for (int i = 0; i < 4; ++i) {
            float2 f = __half22float2(src2[i]);
            dst2[i] = __floats2half2_rn(f.x * QSCALE, f.y * QSCALE);
        }
    }

    float o[8][4];
    #pragma unroll
    for (int nt = 0; nt < 8; ++nt)
        #pragma unroll
        for (int r = 0; r < 4; ++r) o[nt][r] = 0.f;
    float m_0 = -INFINITY, m_1 = -INFINITY, l_0 = 0.f, l_1 = 0.f;

    const __half* kvbase = qkv + ((size_t)(b * LL)) * (3 * DD) + head * (3 * HD) + HD;

    for (int st = 0; st < LL / 64; ++st) {
        __syncthreads();                   // previous-tile reads done
        const int sbase = st * 64;

        // K tile: 64x64 halfs, direct copy (uint4)
        for (int s = tid; s < 64 * 8; s += 256) {
            int r = s >> 3, c = (s & 7) * 8;
            *(uint4*)&Ks[r * QSH + c] =
                *(const uint4*)(kvbase + (size_t)(sbase + r) * (3 * DD) + c);
        }
        // V tile: row-pair packed. Each thread: row-pair sp, 8 cols.
        {
            int sp = tid >> 3, c0 = (tid & 7) * 8;
            const __half2* r0 = (const __half2*)(kvbase + (size_t)(sbase + 2 * sp    ) * (3 * DD) + HD + c0);
            const __half2* r1 = (const __half2*)(kvbase + (size_t)(sbase + 2 * sp + 1) * (3 * DD) + HD + c0);
            uint32_t* dst = &Vp[sp * VPS + c0];
            #pragma unroll
            for (int i = 0; i < 4; ++i) {
                __half2 a = r0[i], bb = r1[i];   // cols c0+2i, c0+2i+1
                dst[2 * i]     = __half_as_ushort(__low2half(a)) |
                                 ((uint32_t)__half_as_ushort(__low2half(bb)) << 16);
                dst[2 * i + 1] = __half_as_ushort(__high2half(a)) |
                                 ((uint32_t)__half_as_ushort(__high2half(bb)) << 16);
            }
        }
        __syncthreads();

        // ---- S' = Qs @ K^T (fp16, 4 k16 steps) ----
        float sacc[8][4];
        #pragma unroll
        for (int nt = 0; nt < 8; ++nt)
            #pragma unroll
            for (int r = 0; r < 4; ++r) sacc[nt][r] = 0.f;

        #pragma unroll
        for (int ks = 0; ks < 4; ++ks) {
            const int kb = ks * 16;
            uint32_t a[4];
            a[0] = *(const uint32_t*)&Qs[(m0 + grp    ) * QSH + kb + 2 * qd];
            a[1] = *(const uint32_t*)&Qs[(m0 + grp + 8) * QSH + kb + 2 * qd];
            a[2] = *(const uint32_t*)&Qs[(m0 + grp    ) * QSH + kb + 2 * qd + 8];
            a[3] = *(const uint32_t*)&Qs[(m0 + grp + 8) * QSH + kb + 2 * qd + 8];
            #pragma unroll
            for (int nt = 0; nt < 8; ++nt) {
                uint32_t bb[2];
                bb[0] = *(const uint32_t*)&Ks[(nt * 8 + grp) * QSH + kb + 2 * qd];
                bb[1] = *(const uint32_t*)&Ks[(nt * 8 + grp) * QSH + kb + 2 * qd + 8];
                MMA_F16(sacc[nt], a, bb);
            }
        }

        // ---- mask (slow path only when tile has zeros) ----
        if (flags[qt * 32 + st] == 0) {
            const int r0g = qbase + m0 + grp, r1g = r0g + 8;
            #pragma unroll
            for (int nt = 0; nt < 8; ++nt) {
                const int c0 = sbase + nt * 8 + 2 * qd;
                if (mask[(size_t)r0g * LL + c0    ] == 0) sacc[nt][0] = -INFINITY;
                if (mask[(size_t)r0g * LL + c0 + 1] == 0) sacc[nt][1] = -INFINITY;
                if (mask[(size_t)r1g * LL + c0    ] == 0) sacc[nt][2] = -INFINITY;
                if (mask[(size_t)r1g * LL + c0 + 1] == 0) sacc[nt][3] = -INFINITY;
            }
        }

        // ---- online softmax (exp2 domain) ----
        float rm0 = -INFINITY, rm1 = -INFINITY;
        #pragma unroll
        for (int nt = 0; nt < 8; ++nt) {
            rm0 = fmaxf(rm0, fmaxf(sacc[nt][0], sacc[nt][1]));
            rm1 = fmaxf(rm1, fmaxf(sacc[nt][2], sacc[nt][3]));
        }
        rm0 = fmaxf(rm0, __shfl_xor_sync(0xffffffffu, rm0, 1));
        rm0 = fmaxf(rm0, __shfl_xor_sync(0xffffffffu, rm0, 2));
        rm1 = fmaxf(rm1, __shfl_xor_sync(0xffffffffu, rm1, 1));
        rm1 = fmaxf(rm1, __shfl_xor_sync(0xffffffffu, rm1, 2));
        const float mn0 = fmaxf(m_0, rm0), mn1 = fmaxf(m_1, rm1);
        const float al0 = exp2f(m_0 - mn0), al1 = exp2f(m_1 - mn1);
        m_0 = mn0; m_1 = mn1;

        // p -> fp16 (rounded BEFORE summation); pack PV A-frags directly
        uint32_t ph[8][2];
        float s0 = 0.f, s1 = 0.f;
        #pragma unroll
        for (int nt = 0; nt < 8; ++nt) {
            __half2 p01 = __floats2half2_rn(exp2f(sacc[nt][0] - mn0),
                                            exp2f(sacc[nt][1] - mn0));
            __half2 p23 = __floats2half2_rn(exp2f(sacc[nt][2] - mn1),
                                            exp2f(sacc[nt][3] - mn1));
            ph[nt][0] = *(uint32_t*)&p01;
            ph[nt][1] = *(uint32_t*)&p23;
            float2 f0 = __half22float2(p01), f1 = __half22float2(p23);
            s0 += f0.x + f0.y; s1 += f1.x + f1.y;
        }
        s0 += __shfl_xor_sync(0xffffffffu, s0, 1);
        s0 += __shfl_xor_sync(0xffffffffu, s0, 2);
        s1 += __shfl_xor_sync(0xffffffffu, s1, 1);
        s1 += __shfl_xor_sync(0xffffffffu, s1, 2);
        l_0 = l_0 * al0 + s0;
        l_1 = l_1 * al1 + s1;
        #pragma unroll
        for (int nt = 0; nt < 8; ++nt) {
            o[nt][0] *= al0; o[nt][1] *= al0;
            o[nt][2] *= al1; o[nt][3] *= al1;
        }

        // ---- O += P @ V (fp16; A-frag = S C-frag, zero shuffles) ----
        #pragma unroll
        for (int ks = 0; ks < 4; ++ks) {
            uint32_t a[4];
            a[0] = ph[2 * ks    ][0];
            a[1] = ph[2 * ks    ][1];
            a[2] = ph[2 * ks + 1][0];
            a[3] = ph[2 * ks + 1][1];
            const int kp = ks * 8;         // Vp row base (= kb/2)
            #pragma unroll
            for (int nt = 0; nt < 8; ++nt) {
                uint32_t bb[2];
                bb[0] = Vp[(kp + qd    ) * VPS + nt * 8 + grp];
                bb[1] = Vp[(kp + qd + 4) * VPS + nt * 8 + grp];
                MMA_F16(o[nt], a, bb);
            }
        }
    }

    // ---- normalize + write fp16 (head-concat [B,L,D]) ----
    const float li0 = 1.f / l_0, li1 = 1.f / l_1;
    const int r0g = qbase + m0 + grp;
    #pragma unroll
    for (int nt = 0; nt < 8; ++nt) {
        const int col = head * HD + nt * 8 + 2 * qd;
        *(__half2*)&hvals[((size_t)(b * LL + r0g    )) * DD + col] =
            __floats2half2_rn(o[nt][0] * li0, o[nt][1] * li0);
        *(__half2*)&hvals[((size_t)(b * LL + r0g + 8)) * DD + col] =
            __floats2half2_rn(o[nt][2] * li1, o[nt][3] * li1);
    }
}

// ---------------------------------------------------------------------------
// Fused residual-add + LayerNorm; optional fp16 copy of the output.
// ---------------------------------------------------------------------------
template<int WH>
__global__ __launch_bounds__(128)
void add_ln(const float* __restrict__ a, const float* __restrict__ bres,
            const float* __restrict__ g, const float* __restrict__ beta,
            float* __restrict__ out, __half* __restrict__ hout)
{
    const int row = blockIdx.x;
    const int tid = threadIdx.x;

    float4 av = ((const float4*)(a    + (size_t)row * DD))[tid];
    float4 bv = ((const float4*)(bres + (size_t)row * DD))[tid];
    float4 x = make_float4(av.x+bv.x, av.y+bv.y, av.z+bv.z, av.w+bv.w);

    float s  = x.x + x.y + x.z + x.w;
    float ss = x.x*x.x + x.y*x.y + x.z*x.z + x.w*x.w;

    #pragma unroll
    for (int o = 16; o > 0; o >>= 1) {
        s  += __shfl_xor_sync(0xffffffffu, s,  o);
        ss += __shfl_xor_sync(0xffffffffu, ss, o);
    }
    __shared__ float red[2][4];
    const int w = tid >> 5, l = tid & 31;
    if (l == 0) { red[0][w] = s; red[1][w] = ss; }
    __syncthreads();
    s  = red[0][0] + red[0][1] + red[0][2] + red[0][3];
    ss = red[1][0] + red[1][1] + red[1][2] + red[1][3];

    const float mean = s * (1.f / DD);
    const float var  = ss * (1.f / DD) - mean * mean;
    const float rstd = rsqrtf(var + 1e-5f);

    float4 gv = ((const float4*)g)[tid];
    float4 ev = ((const float4*)beta)[tid];
    float4 o;
    o.x = (x.x - mean) * rstd * gv.x + ev.x;
    o.y = (x.y - mean) * rstd * gv.y + ev.y;
    o.z = (x.z - mean) * rstd * gv.z + ev.z;
    o.w = (x.w - mean) * rstd * gv.w + ev.w;
    ((float4*)(out + (size_t)row * DD))[tid] = o;
    if (WH) {
        *(__half2*)(hout + (size_t)row * DD + tid * 4)     = __floats2half2_rn(o.x, o.y);
        *(__half2*)(hout + (size_t)row * DD + tid * 4 + 2) = __floats2half2_rn(o.z, o.w);
    }
}

// ---------------------------------------------------------------------------
extern "C" void kernel_launch(void* const* d_in, const int* in_sizes, int n_in,
                              void* d_out, int out_size)
{
    const float* src    = (const float*)d_in[0];
    const int*   mask   = (const int*)  d_in[1];
    const float* qkv_w  = (const float*)d_in[2];
    const float* qkv_b  = (const float*)d_in[3];
    const float* out_w  = (const float*)d_in[4];
    const float* out_b  = (const float*)d_in[5];
    const float* w1     = (const float*)d_in[6];
    const float* b1     = (const float*)d_in[7];
    const float* w2     = (const float*)d_in[8];
    const float* b2     = (const float*)d_in[9];
    const float* g1     = (const float*)d_in[10];
    const float* beta1  = (const float*)d_in[11];
    const float* g2     = (const float*)d_in[12];
    const float* beta2  = (const float*)d_in[13];
    float* out = (float*)d_out;

    void* p;
    cudaGetSymbolAddress(&p, g_tmp);   float*  tmp   = (float*)p;
    cudaGetSymbolAddress(&p, g_x1);    float*  x1    = (float*)p;
    cudaGetSymbolAddress(&p, g_mflag); int*    mflag = (int*)p;
    cudaGetSymbolAddress(&p, h_qkv);   __half* hqkv  = (__half*)p;
    cudaGetSymbolAddress(&p, h_src);   __half* hsrc  = (__half*)p;
    cudaGetSymbolAddress(&p, h_qkvw);  __half* hqkvw = (__half*)p;
    cudaGetSymbolAddress(&p, h_outw);  __half* houtw = (__half*)p;
    cudaGetSymbolAddress(&p, h_w1);    __half* hw1   = (__half*)p;
    cudaGetSymbolAddress(&p, h_w2);    __half* hw2   = (__half*)p;
    cudaGetSymbolAddress(&p, h_vals);  __half* hvals = (__half*)p;
    cudaGetSymbolAddress(&p, h_x1);    __half* hx1   = (__half*)p;
    cudaGetSymbolAddress(&p, h_ff);    __half* hff   = (__half*)p;

    cudaFuncSetAttribute(mma_gemm<0,0>, cudaFuncAttributeMaxDynamicSharedMemorySize, GEMM_SMEM);
    cudaFuncSetAttribute(mma_gemm<0,1>, cudaFuncAttributeMaxDynamicSharedMemorySize, GEMM_SMEM);
    cudaFuncSetAttribute(mma_gemm<1,1>, cudaFuncAttributeMaxDynamicSharedMemorySize, GEMM_SMEM);
    cudaFuncSetAttribute(flash_attn_mma, cudaFuncAttributeMaxDynamicSharedMemorySize, ATT_SMEM);

    // 0) operand conversions + mask flags
    f2h<<<256, 256>>>(src,   hsrc,  MR * DD);
    f2h<<<128, 256>>>(qkv_w, hqkvw, 3 * DD * DD);
    f2h<<<64,  256>>>(out_w, houtw, DD * DD);
    f2h<<<128, 256>>>(w1,    hw1,   DFF * DD);
    f2h<<<128, 256>>>(w2,    hw2,   DD * DFF);
    mask_flags<<<512, 256>>>(mask, mflag);

    // 1) QKV projection (fp16 in, fp16 out)
    mma_gemm<0,1><<<dim3((3*DD)/128, MR/128), 256, GEMM_SMEM>>>(
        hsrc, hqkvw, qkv_b, nullptr, hqkv, MR, 3*DD, DD);

    // 2) flash attention (all-fp16 mma) -> h_vals
    flash_attn_mma<<<dim3(LL/128, HH, BB), 256, ATT_SMEM>>>(hqkv, mask, mflag, hvals);

    // 3) output projection (fp16 in, fp32 out)
    mma_gemm<0,0><<<dim3(DD/128, MR/128), 256, GEMM_SMEM>>>(
        hvals, houtw, out_b, tmp, nullptr, MR, DD, DD);

    // 4) x1 = LN(src + proj), also fp16 copy
    add_ln<1><<<MR, 128>>>(src, tmp, g1, beta1, x1, hx1);

    // 5) FFN1 + ReLU (fp16 in, fp16 out)
    mma_gemm<1,1><<<dim3(DFF/128, MR/128), 256, GEMM_SMEM>>>(
        hx1, hw1, b1, nullptr, hff, MR, DFF, DD);

    // 6) FFN2 (fp16 in, fp32 out)
    mma_gemm<0,0><<<dim3(DD/128, MR/128), 256, GEMM_SMEM>>>(
        hff, hw2, b2, tmp, nullptr, MR, DD, DFF);

    // 7) out = LN(x1 + ffn2)
    add_ln<0><<<MR, 128>>>(x1, tmp, g2, beta2, out, nullptr);
}

// round 16
// speedup vs baseline: 1.7179x; 1.0291x over previous
#include <cuda_runtime.h>
#include <cuda_fp16.h>
#include <math.h>
#include <stdint.h>

// Problem constants
#define BB   4
#define LL   2048
#define DD   512
#define HH   8
#define HD   64
#define DFF  2048
#define MR   (BB*LL)   // 8192 rows

// ---------------- scratch (device globals: allocation-free) ----------------
__device__ float  g_tmp [MR * DD];
__device__ float  g_x1  [MR * DD];
__device__ int    g_mflag[16 * 32];
__device__ __half h_qkv [MR * 3 * DD];
__device__ __half h_src [MR * DD];
__device__ __half h_qkvw[3 * DD * DD];
__device__ __half h_outw[DD * DD];
__device__ __half h_w1  [DFF * DD];
__device__ __half h_w2  [DD * DFF];
__device__ __half h_vals[MR * DD];
__device__ __half h_x1  [MR * DD];
__device__ __half h_ff  [MR * DFF];

// ---------------------------------------------------------------------------
// helpers
// ---------------------------------------------------------------------------
__device__ __forceinline__ uint32_t smem_u32(const void* p) {
    uint32_t a;
    asm("{ .reg .u64 t; cvta.to.shared.u64 t, %1; cvt.u32.u64 %0, t; }"
        : "=r"(a) : "l"(p));
    return a;
}

#define MMA_F16(d, a, b)                                                       \
    asm volatile("mma.sync.aligned.m16n8k16.row.col.f32.f16.f16.f32 "          \
        "{%0,%1,%2,%3}, {%4,%5,%6,%7}, {%8,%9}, {%0,%1,%2,%3};"                \
        : "+f"((d)[0]), "+f"((d)[1]), "+f"((d)[2]), "+f"((d)[3])               \
        : "r"((a)[0]), "r"((a)[1]), "r"((a)[2]), "r"((a)[3]),                  \
          "r"((b)[0]), "r"((b)[1]))

#define LDSM_X4(r0, r1, r2, r3, addr)                                          \
    asm volatile("ldmatrix.sync.aligned.m8n8.x4.shared.b16 {%0,%1,%2,%3}, [%4];" \
        : "=r"(r0), "=r"(r1), "=r"(r2), "=r"(r3) : "r"(addr))

#define CP_ASYNC16(dst, src)                                                   \
    asm volatile("cp.async.cg.shared.global [%0], [%1], 16;"                   \
        :: "r"(dst), "l"(src) : "memory")
#define CP_COMMIT() asm volatile("cp.async.commit_group;" ::: "memory")
#define CP_WAIT(n)  asm volatile("cp.async.wait_group %0;" :: "n"(n) : "memory")

// ---------------------------------------------------------------------------
// fp32 -> fp16 conversion (vectorized)
// ---------------------------------------------------------------------------
__global__ __launch_bounds__(256)
void f2h(const float* __restrict__ in, __half* __restrict__ out, int n)
{
    int i = (blockIdx.x * 256 + threadIdx.x) * 4;
    const int stride = gridDim.x * 256 * 4;
    for (; i < n; i += stride) {
        float4 v = *(const float4*)(in + i);
        *(__half2*)(out + i)     = __floats2half2_rn(v.x, v.y);
        *(__half2*)(out + i + 2) = __floats2half2_rn(v.z, v.w);
    }
}

// ---------------------------------------------------------------------------
// fp16 mma.sync GEMM v5: m16n8k16, BK=32, 3-stage cp.async,
// ldmatrix fragment loads (12 LDSM vs 48 LDS per warp-stage),
// prefetch issued immediately after the stage barrier.
// GPAD=40 halfs: ldmatrix 8-row phases hit banks {20k mod 32}+0..3 = all 32.
// ---------------------------------------------------------------------------
#define GPAD 40
#define GTILE (128 * GPAD)
#define GSTG 3
#define GEMM_SMEM (GSTG * 2 * GTILE * 2)    // 61440 bytes

template<int RELU, int OUTH>
__global__ __launch_bounds__(256, 2)
void mma_gemm(const __half* __restrict__ A, const __half* __restrict__ W,
              const float* __restrict__ bias, float* __restrict__ C,
              __half* __restrict__ CH, int M, int N, int K)
{
    extern __shared__ __half gsm[];

    const int tid  = threadIdx.x;
    const int wid  = tid >> 5, lane = tid & 31;
    const int grp  = lane >> 2, qd = lane & 3;
    const int wm   = (wid & 1) * 64;
    const int wn   = (wid >> 1) * 32;
    const int bm   = blockIdx.y * 128;
    const int bn   = blockIdx.x * 128;

    const int lrow = tid >> 1;
    const int lk16 = (tid & 1) * 16;

    const __half* Ap = A + (size_t)(bm + lrow) * K + lk16;
    const __half* Wp = W + (size_t)(bn + lrow) * K + lk16;

    uint32_t sAw[GSTG], sBw[GSTG];
    // ldmatrix lane-address bases per stage buffer
    uint32_t aLd[GSTG], bLd[GSTG];
    const int arow = lane & 15;               // A: row within 16-row tile
    const int acol = (lane >> 4) << 3;        // A: k offset 0/8
    const int brow = (lane & 7) + (((lane >> 4) & 1) << 3);  // B: n within pair
    const int bcol = ((lane >> 3) & 1) << 3;  // B: k offset 0/8
    #pragma unroll
    for (int b = 0; b < GSTG; ++b) {
        sAw[b] = smem_u32(gsm + (2 * b    ) * GTILE + lrow * GPAD + lk16);
        sBw[b] = smem_u32(gsm + (2 * b + 1) * GTILE + lrow * GPAD + lk16);
        aLd[b] = smem_u32(gsm + (2 * b    ) * GTILE) + (((wm + arow) * GPAD + acol) << 1);
        bLd[b] = smem_u32(gsm + (2 * b + 1) * GTILE) + (((wn + brow) * GPAD + bcol) << 1);
    }

    const int NS = K >> 5;

    auto issue = [&](int s, int b) {
        const __half* as = Ap + (size_t)s * 32;
        const __half* ws = Wp + (size_t)s * 32;
        CP_ASYNC16(sAw[b],      as);
        CP_ASYNC16(sAw[b] + 16, as + 8);
        CP_ASYNC16(sBw[b],      ws);
        CP_ASYNC16(sBw[b] + 16, ws + 8);
    };

    issue(0, 0); CP_COMMIT();
    issue(1, 1); CP_COMMIT();

    float acc[4][4][4];
    #pragma unroll
    for (int i = 0; i < 4; i++)
        #pragma unroll
        for (int j = 0; j < 4; j++)
            #pragma unroll
            for (int r = 0; r < 4; r++) acc[i][j][r] = 0.f;

    const int MTSTEP = 16 * GPAD * 2;         // byte stride between 16-row tiles

    for (int s = 0; s < NS; ++s) {
        CP_WAIT(1);
        __syncthreads();

        // prefetch for s+2 goes out FIRST — full stage of latency cover
        if (s + 2 < NS) issue(s + 2, (s + 2) % GSTG);
        CP_COMMIT();

        const int pb = s % GSTG;
        const uint32_t aB = aLd[pb], bB = bLd[pb];

        #pragma unroll
        for (int ks = 0; ks < 2; ++ks) {
            const uint32_t ko = ks * 32;      // 16 halfs = 32 bytes
            uint32_t af[4][4], bf[4][2];
            #pragma unroll
            for (int mt = 0; mt < 4; ++mt)
                LDSM_X4(af[mt][0], af[mt][1], af[mt][2], af[mt][3],
                        aB + mt * MTSTEP + ko);
            #pragma unroll
            for (int pr = 0; pr < 2; ++pr)
                LDSM_X4(bf[2*pr][0], bf[2*pr][1], bf[2*pr+1][0], bf[2*pr+1][1],
                        bB + pr * MTSTEP + ko);
            #pragma unroll
            for (int mt = 0; mt < 4; ++mt)
                #pragma unroll
                for (int nt = 0; nt < 4; ++nt)
                    MMA_F16(acc[mt][nt], af[mt], bf[nt]);
        }
    }

    #pragma unroll
    for (int mt = 0; mt < 4; ++mt) {
        const int row = bm + wm + mt * 16 + grp;
        #pragma unroll
        for (int nt = 0; nt < 4; ++nt) {
            const int col = bn + wn + nt * 8 + 2 * qd;
            const float2 bv = *(const float2*)&bias[col];
            float2 o0, o1;
            o0.x = acc[mt][nt][0] + bv.x; o0.y = acc[mt][nt][1] + bv.y;
            o1.x = acc[mt][nt][2] + bv.x; o1.y = acc[mt][nt][3] + bv.y;
            if (RELU) {
                o0.x = fmaxf(o0.x, 0.f); o0.y = fmaxf(o0.y, 0.f);
                o1.x = fmaxf(o1.x, 0.f); o1.y = fmaxf(o1.y, 0.f);
            }
            if (OUTH) {
                *(__half2*)(CH + (size_t)row * N + col)       = __floats2half2_rn(o0.x, o0.y);
                *(__half2*)(CH + (size_t)(row + 8) * N + col) = __floats2half2_rn(o1.x, o1.y);
            } else {
                *(float2*)(C + (size_t)row * N + col)       = o0;
                *(float2*)(C + (size_t)(row + 8) * N + col) = o1;
            }
        }
    }
}

// ---------------------------------------------------------------------------
// mask tile flags (unchanged).
// ---------------------------------------------------------------------------
__global__ __launch_bounds__(256)
void mask_flags(const int* __restrict__ mask, int* __restrict__ flags)
{
    const int idx = blockIdx.x;
    const int qt = idx >> 5, st = idx & 31;
    const int tid = threadIdx.x;
    int ok = 1;
    for (int i = tid; i < 128 * 64; i += 256) {
        int r = qt * 128 + (i >> 6);
        int c = st * 64 + (i & 63);
        ok &= (mask[(size_t)r * LL + c] != 0);
    }
    int all = __syncthreads_and(ok);
    if (tid == 0) flags[idx] = all;
}

// ---------------------------------------------------------------------------
// Flash attention v3 (R15-exact, the proven 523us version).
// ---------------------------------------------------------------------------
#define QSH 72
#define VPS 72
#define ATT_SMEM ((128 * QSH + 64 * QSH) * 2 + 32 * VPS * 4)   // 36864 B

__global__ __launch_bounds__(256)
void flash_attn_mma(const __half* __restrict__ qkv, const int* __restrict__ mask,
                    const int* __restrict__ flags, __half* __restrict__ hvals)
{
    extern __shared__ char asm_raw[];
    __half*   Qs = (__half*)asm_raw;                      // [128][QSH]
    __half*   Ks = Qs + 128 * QSH;                        // [64][QSH]
    uint32_t* Vp = (uint32_t*)(Ks + 64 * QSH);            // [32][VPS]

    const int tid  = threadIdx.x;
    const int wid  = tid >> 5, lane = tid & 31;
    const int grp  = lane >> 2, qd = lane & 3;
    const int qt   = blockIdx.x;
    const int head = blockIdx.y;
    const int b    = blockIdx.z;
    const int qbase = qt * 128;
    const int m0   = wid * 16;

    const float QSCALE = 0.125f * 1.44269504088896340736f;

    const __half* qp = qkv + ((size_t)(b * LL + qbase)) * (3 * DD) + head * (3 * HD);
    for (int s = tid; s < 128 * 8; s += 256) {
        int r = s >> 3, c = (s & 7) * 8;
        const __half2* src2 = (const __half2*)(qp + (size_t)r * (3 * DD) + c);
        __half2* dst2 = (__half2*)&Qs[r * QSH + c];
        #pragma unroll
        for (int i = 0; i < 4; ++i) {
            float2 f = __half22float2(src2[i]);
            dst2[i] = __floats2half2_rn(f.x * QSCALE, f.y * QSCALE);
        }
    }

    float o[8][4];
    #pragma unroll
    for (int nt = 0; nt < 8; ++nt)
        #pragma unroll
        for (int r = 0; r < 4; ++r) o[nt][r] = 0.f;
    float m_0 = -INFINITY, m_1 = -INFINITY, l_0 = 0.f, l_1 = 0.f;

    const __half* kvbase = qkv + ((size_t)(b * LL)) * (3 * DD) + head * (3 * HD) + HD;

    for (int st = 0; st < LL / 64; ++st) {
        __syncthreads();
        const int sbase = st * 64;

        for (int s = tid; s < 64 * 8; s += 256) {
            int r = s >> 3, c = (s & 7) * 8;
            *(uint4*)&Ks[r * QSH + c] =
                *(const uint4*)(kvbase + (size_t)(sbase + r) * (3 * DD) + c);
        }
        {
            int sp = tid >> 3, c0 = (tid & 7) * 8;
            const __half2* r0 = (const __half2*)(kvbase + (size_t)(sbase + 2 * sp    ) * (3 * DD) + HD + c0);
            const __half2* r1 = (const __half2*)(kvbase + (size_t)(sbase + 2 * sp + 1) * (3 * DD) + HD + c0);
            uint32_t* dst = &Vp[sp * VPS + c0];
            #pragma unroll
            for (int i = 0; i < 4; ++i) {
                __half2 a = r0[i], bb = r1[i];
                dst[2 * i]     = __half_as_ushort(__low2half(a)) |
                                 ((uint32_t)__half_as_ushort(__low2half(bb)) << 16);
                dst[2 * i + 1] = __half_as_ushort(__high2half(a)) |
                                 ((uint32_t)__half_as_ushort(__high2half(bb)) << 16);
            }
        }
        __syncthreads();

        float sacc[8][4];
        #pragma unroll
        for (int nt = 0; nt < 8; ++nt)
            #pragma unroll
            for (int r = 0; r < 4; ++r) sacc[nt][r] = 0.f;

        #pragma unroll
        for (int ks = 0; ks < 4; ++ks) {
            const int kb = ks * 16;
            uint32_t a[4];
            a[0] = *(const uint32_t*)&Qs[(m0 + grp    ) * QSH + kb + 2 * qd];
            a[1] = *(const uint32_t*)&Qs[(m0 + grp + 8) * QSH + kb + 2 * qd];
            a[2] = *(const uint32_t*)&Qs[(m0 + grp    ) * QSH + kb + 2 * qd + 8];
            a[3] = *(const uint32_t*)&Qs[(m0 + grp + 8) * QSH + kb + 2 * qd + 8];
            #pragma unroll
            for (int nt = 0; nt < 8; ++nt) {
                uint32_t bb[2];
                bb[0] = *(const uint32_t*)&Ks[(nt * 8 + grp) * QSH + kb + 2 * qd];
                bb[1] = *(const uint32_t*)&Ks[(nt * 8 + grp) * QSH + kb + 2 * qd + 8];
                MMA_F16(sacc[nt], a, bb);
            }
        }

        if (flags[qt * 32 + st] == 0) {
            const int r0g = qbase + m0 + grp, r1g = r0g + 8;
            #pragma unroll
            for (int nt = 0; nt < 8; ++nt) {
                const int c0 = sbase + nt * 8 + 2 * qd;
                if (mask[(size_t)r0g * LL + c0    ] == 0) sacc[nt][0] = -INFINITY;
                if (mask[(size_t)r0g * LL + c0 + 1] == 0) sacc[nt][1] = -INFINITY;
                if (mask[(size_t)r1g * LL + c0    ] == 0) sacc[nt][2] = -INFINITY;
                if (mask[(size_t)r1g * LL + c0 + 1] == 0) sacc[nt][3] = -INFINITY;
            }
        }

        float rm0 = -INFINITY, rm1 = -INFINITY;
        #pragma unroll
        for (int nt = 0; nt < 8; ++nt) {
            rm0 = fmaxf(rm0, fmaxf(sacc[nt][0], sacc[nt][1]));
            rm1 = fmaxf(rm1, fmaxf(sacc[nt][2], sacc[nt][3]));
        }
        rm0 = fmaxf(rm0, __shfl_xor_sync(0xffffffffu, rm0, 1));
        rm0 = fmaxf(rm0, __shfl_xor_sync(0xffffffffu, rm0, 2));
        rm1 = fmaxf(rm1, __shfl_xor_sync(0xffffffffu, rm1, 1));
        rm1 = fmaxf(rm1, __shfl_xor_sync(0xffffffffu, rm1, 2));
        const float mn0 = fmaxf(m_0, rm0), mn1 = fmaxf(m_1, rm1);
        const float al0 = exp2f(m_0 - mn0), al1 = exp2f(m_1 - mn1);
        m_0 = mn0; m_1 = mn1;

        uint32_t ph[8][2];
        float s0 = 0.f, s1 = 0.f;
        #pragma unroll
        for (int nt = 0; nt < 8; ++nt) {
            __half2 p01 = __floats2half2_rn(exp2f(sacc[nt][0] - mn0),
                                            exp2f(sacc[nt][1] - mn0));
            __half2 p23 = __floats2half2_rn(exp2f(sacc[nt][2] - mn1),
                                            exp2f(sacc[nt][3] - mn1));
            ph[nt][0] = *(uint32_t*)&p01;
            ph[nt][1] = *(uint32_t*)&p23;
            float2 f0 = __half22float2(p01), f1 = __half22float2(p23);
            s0 += f0.x + f0.y; s1 += f1.x + f1.y;
        }
        s0 += __shfl_xor_sync(0xffffffffu, s0, 1);
        s0 += __shfl_xor_sync(0xffffffffu, s0, 2);
        s1 += __shfl_xor_sync(0xffffffffu, s1, 1);
        s1 += __shfl_xor_sync(0xffffffffu, s1, 2);
        l_0 = l_0 * al0 + s0;
        l_1 = l_1 * al1 + s1;
        #pragma unroll
        for (int nt = 0; nt < 8; ++nt) {
            o[nt][0] *= al0; o[nt][1] *= al0;
            o[nt][2] *= al1; o[nt][3] *= al1;
        }

        #pragma unroll
        for (int ks = 0; ks < 4; ++ks) {
            uint32_t a[4];
            a[0] = ph[2 * ks    ][0];
            a[1] = ph[2 * ks    ][1];
            a[2] = ph[2 * ks + 1][0];
            a[3] = ph[2 * ks + 1][1];
            const int kp = ks * 8;
            #pragma unroll
            for (int nt = 0; nt < 8; ++nt) {
                uint32_t bb[2];
                bb[0] = Vp[(kp + qd    ) * VPS + nt * 8 + grp];
                bb[1] = Vp[(kp + qd + 4) * VPS + nt * 8 + grp];
                MMA_F16(o[nt], a, bb);
            }
        }
    }

    const float li0 = 1.f / l_0, li1 = 1.f / l_1;
    const int r0g = qbase + m0 + grp;
    #pragma unroll
    for (int nt = 0; nt < 8; ++nt) {
        const int col = head * HD + nt * 8 + 2 * qd;
        *(__half2*)&hvals[((size_t)(b * LL + r0g    )) * DD + col] =
            __floats2half2_rn(o[nt][0] * li0, o[nt][1] * li0);
        *(__half2*)&hvals[((size_t)(b * LL + r0g + 8)) * DD + col] =
            __floats2half2_rn(o[nt][2] * li1, o[nt][3] * li1);
    }
}

// ---------------------------------------------------------------------------
// Fused residual-add + LayerNorm; optional fp16 copy of the output.
// ---------------------------------------------------------------------------
template<int WH>
__global__ __launch_bounds__(128)
void add_ln(const float* __restrict__ a, const float* __restrict__ bres,
            const float* __restrict__ g, const float* __restrict__ beta,
            float* __restrict__ out, __half* __restrict__ hout)
{
    const int row = blockIdx.x;
    const int tid = threadIdx.x;

    float4 av = ((const float4*)(a    + (size_t)row * DD))[tid];
    float4 bv = ((const float4*)(bres + (size_t)row * DD))[tid];
    float4 x = make_float4(av.x+bv.x, av.y+bv.y, av.z+bv.z, av.w+bv.w);

    float s  = x.x + x.y + x.z + x.w;
    float ss = x.x*x.x + x.y*x.y + x.z*x.z + x.w*x.w;

    #pragma unroll
    for (int o = 16; o > 0; o >>= 1) {
        s  += __shfl_xor_sync(0xffffffffu, s,  o);
        ss += __shfl_xor_sync(0xffffffffu, ss, o);
    }
    __shared__ float red[2][4];
    const int w = tid >> 5, l = tid & 31;
    if (l == 0) { red[0][w] = s; red[1][w] = ss; }
    __syncthreads();
    s  = red[0][0] + red[0][1] + red[0][2] + red[0][3];
    ss = red[1][0] + red[1][1] + red[1][2] + red[1][3];

    const float mean = s * (1.f / DD);
    const float var  = ss * (1.f / DD) - mean * mean;
    const float rstd = rsqrtf(var + 1e-5f);

    float4 gv = ((const float4*)g)[tid];
    float4 ev = ((const float4*)beta)[tid];
    float4 o;
    o.x = (x.x - mean) * rstd * gv.x + ev.x;
    o.y = (x.y - mean) * rstd * gv.y + ev.y;
    o.z = (x.z - mean) * rstd * gv.z + ev.z;
    o.w = (x.w - mean) * rstd * gv.w + ev.w;
    ((float4*)(out + (size_t)row * DD))[tid] = o;
    if (WH) {
        *(__half2*)(hout + (size_t)row * DD + tid * 4)     = __floats2half2_rn(o.x, o.y);
        *(__half2*)(hout + (size_t)row * DD + tid * 4 + 2) = __floats2half2_rn(o.z, o.w);
    }
}

// ---------------------------------------------------------------------------
extern "C" void kernel_launch(void* const* d_in, const int* in_sizes, int n_in,
                              void* d_out, int out_size)
{
    const float* src    = (const float*)d_in[0];
    const int*   mask   = (const int*)  d_in[1];
    const float* qkv_w  = (const float*)d_in[2];
    const float* qkv_b  = (const float*)d_in[3];
    const float* out_w  = (const float*)d_in[4];
    const float* out_b  = (const float*)d_in[5];
    const float* w1     = (const float*)d_in[6];
    const float* b1     = (const float*)d_in[7];
    const float* w2     = (const float*)d_in[8];
    const float* b2     = (const float*)d_in[9];
    const float* g1     = (const float*)d_in[10];
    const float* beta1  = (const float*)d_in[11];
    const float* g2     = (const float*)d_in[12];
    const float* beta2  = (const float*)d_in[13];
    float* out = (float*)d_out;

    void* p;
    cudaGetSymbolAddress(&p, g_tmp);   float*  tmp   = (float*)p;
    cudaGetSymbolAddress(&p, g_x1);    float*  x1    = (float*)p;
    cudaGetSymbolAddress(&p, g_mflag); int*    mflag = (int*)p;
    cudaGetSymbolAddress(&p, h_qkv);   __half* hqkv  = (__half*)p;
    cudaGetSymbolAddress(&p, h_src);   __half* hsrc  = (__half*)p;
    cudaGetSymbolAddress(&p, h_qkvw);  __half* hqkvw = (__half*)p;
    cudaGetSymbolAddress(&p, h_outw);  __half* houtw = (__half*)p;
    cudaGetSymbolAddress(&p, h_w1);    __half* hw1   = (__half*)p;
    cudaGetSymbolAddress(&p, h_w2);    __half* hw2   = (__half*)p;
    cudaGetSymbolAddress(&p, h_vals);  __half* hvals = (__half*)p;
    cudaGetSymbolAddress(&p, h_x1);    __half* hx1   = (__half*)p;
    cudaGetSymbolAddress(&p, h_ff);    __half* hff   = (__half*)p;

    cudaFuncSetAttribute(mma_gemm<0,0>, cudaFuncAttributeMaxDynamicSharedMemorySize, GEMM_SMEM);
    cudaFuncSetAttribute(mma_gemm<0,1>, cudaFuncAttributeMaxDynamicSharedMemorySize, GEMM_SMEM);
    cudaFuncSetAttribute(mma_gemm<1,1>, cudaFuncAttributeMaxDynamicSharedMemorySize, GEMM_SMEM);
    cudaFuncSetAttribute(flash_attn_mma, cudaFuncAttributeMaxDynamicSharedMemorySize, ATT_SMEM);

    // 0) operand conversions + mask flags
    f2h<<<256, 256>>>(src,   hsrc,  MR * DD);
    f2h<<<128, 256>>>(qkv_w, hqkvw, 3 * DD * DD);
    f2h<<<64,  256>>>(out_w, houtw, DD * DD);
    f2h<<<128, 256>>>(w1,    hw1,   DFF * DD);
    f2h<<<128, 256>>>(w2,    hw2,   DD * DFF);
    mask_flags<<<512, 256>>>(mask, mflag);

    // 1) QKV projection (fp16 in, fp16 out)
    mma_gemm<0,1><<<dim3((3*DD)/128, MR/128), 256, GEMM_SMEM>>>(
        hsrc, hqkvw, qkv_b, nullptr, hqkv, MR, 3*DD, DD);

    // 2) flash attention (all-fp16 mma) -> h_vals
    flash_attn_mma<<<dim3(LL/128, HH, BB), 256, ATT_SMEM>>>(hqkv, mask, mflag, hvals);

    // 3) output projection (fp16 in, fp32 out)
    mma_gemm<0,0><<<dim3(DD/128, MR/128), 256, GEMM_SMEM>>>(
        hvals, houtw, out_b, tmp, nullptr, MR, DD, DD);

    // 4) x1 = LN(src + proj), also fp16 copy
    add_ln<1><<<MR, 128>>>(src, tmp, g1, beta1, x1, hx1);

    // 5) FFN1 + ReLU (fp16 in, fp16 out)
    mma_gemm<1,1><<<dim3(DFF/128, MR/128), 256, GEMM_SMEM>>>(
        hx1, hw1, b1, nullptr, hff, MR, DFF, DD);

    // 6) FFN2 (fp16 in, fp32 out)
    mma_gemm<0,0><<<dim3(DD/128, MR/128), 256, GEMM_SMEM>>>(
        hff, hw2, b2, tmp, nullptr, MR, DD, DFF);

    // 7) out = LN(x1 + ffn2)
    add_ln<0><<<MR, 128>>>(x1, tmp, g2, beta2, out, nullptr);
}

// round 17
// speedup vs baseline: 1.7533x; 1.0206x over previous
#include <cuda_runtime.h>
#include <cuda_fp16.h>
#include <math.h>
#include <stdint.h>

// Problem constants
#define BB   4
#define LL   2048
#define DD   512
#define HH   8
#define HD   64
#define DFF  2048
#define MR   (BB*LL)   // 8192 rows

// ---------------- scratch (device globals: allocation-free) ----------------
__device__ float  g_tmp [MR * DD];
__device__ float  g_x1  [MR * DD];
__device__ int    g_mflag[16 * 32];
__device__ __half h_qkv [MR * 3 * DD];
__device__ __half h_src [MR * DD];
__device__ __half h_qkvw[3 * DD * DD];
__device__ __half h_outw[DD * DD];
__device__ __half h_w1  [DFF * DD];
__device__ __half h_w2  [DD * DFF];
__device__ __half h_vals[MR * DD];
__device__ __half h_x1  [MR * DD];
__device__ __half h_ff  [MR * DFF];

// ---------------------------------------------------------------------------
// helpers
// ---------------------------------------------------------------------------
__device__ __forceinline__ uint32_t smem_u32(const void* p) {
    uint32_t a;
    asm("{ .reg .u64 t; cvta.to.shared.u64 t, %1; cvt.u32.u64 %0, t; }"
        : "=r"(a) : "l"(p));
    return a;
}

#define MMA_F16(d, a, b)                                                       \
    asm volatile("mma.sync.aligned.m16n8k16.row.col.f32.f16.f16.f32 "          \
        "{%0,%1,%2,%3}, {%4,%5,%6,%7}, {%8,%9}, {%0,%1,%2,%3};"                \
        : "+f"((d)[0]), "+f"((d)[1]), "+f"((d)[2]), "+f"((d)[3])               \
        : "r"((a)[0]), "r"((a)[1]), "r"((a)[2]), "r"((a)[3]),                  \
          "r"((b)[0]), "r"((b)[1]))

#define LDSM_X4(r0, r1, r2, r3, addr)                                          \
    asm volatile("ldmatrix.sync.aligned.m8n8.x4.shared.b16 {%0,%1,%2,%3}, [%4];" \
        : "=r"(r0), "=r"(r1), "=r"(r2), "=r"(r3) : "r"(addr))

#define CP_ASYNC16(dst, src)                                                   \
    asm volatile("cp.async.cg.shared.global [%0], [%1], 16;"                   \
        :: "r"(dst), "l"(src) : "memory")
#define CP_COMMIT() asm volatile("cp.async.commit_group;" ::: "memory")
#define CP_WAIT(n)  asm volatile("cp.async.wait_group %0;" :: "n"(n) : "memory")

// ---------------------------------------------------------------------------
// fp32 -> fp16 conversion (vectorized); single-tensor and fused-4 variants
// ---------------------------------------------------------------------------
__global__ __launch_bounds__(256)
void f2h(const float* __restrict__ in, __half* __restrict__ out, int n)
{
    int i = (blockIdx.x * 256 + threadIdx.x) * 4;
    const int stride = gridDim.x * 256 * 4;
    for (; i < n; i += stride) {
        float4 v = *(const float4*)(in + i);
        *(__half2*)(out + i)     = __floats2half2_rn(v.x, v.y);
        *(__half2*)(out + i + 2) = __floats2half2_rn(v.z, v.w);
    }
}

__global__ __launch_bounds__(256)
void f2h4(const float* __restrict__ s0, __half* __restrict__ d0, int n0,
          const float* __restrict__ s1, __half* __restrict__ d1, int n1,
          const float* __restrict__ s2, __half* __restrict__ d2, int n2,
          const float* __restrict__ s3, __half* __restrict__ d3, int n3)
{
    const int total = n0 + n1 + n2 + n3;
    int i = (blockIdx.x * 256 + threadIdx.x) * 4;
    const int stride = gridDim.x * 256 * 4;
    for (; i < total; i += stride) {
        const float* sp; __half* dp; int off = i;
        if (off < n0)                { sp = s0; dp = d0; }
        else if ((off -= n0) < n1)   { sp = s1; dp = d1; }
        else if ((off -= n1) < n2)   { sp = s2; dp = d2; }
        else { off -= n2;              sp = s3; dp = d3; }
        float4 v = *(const float4*)(sp + off);
        *(__half2*)(dp + off)     = __floats2half2_rn(v.x, v.y);
        *(__half2*)(dp + off + 2) = __floats2half2_rn(v.z, v.w);
    }
}

// ---------------------------------------------------------------------------
// fp16 mma.sync GEMM (R16-exact champion): m16n8k16, BK=32, 3-stage cp.async,
// ldmatrix fragment loads, prefetch first after barrier.
// ---------------------------------------------------------------------------
#define GPAD 40
#define GTILE (128 * GPAD)
#define GSTG 3
#define GEMM_SMEM (GSTG * 2 * GTILE * 2)    // 61440 bytes

template<int RELU, int OUTH>
__global__ __launch_bounds__(256, 2)
void mma_gemm(const __half* __restrict__ A, const __half* __restrict__ W,
              const float* __restrict__ bias, float* __restrict__ C,
              __half* __restrict__ CH, int M, int N, int K)
{
    extern __shared__ __half gsm[];

    const int tid  = threadIdx.x;
    const int wid  = tid >> 5, lane = tid & 31;
    const int grp  = lane >> 2, qd = lane & 3;
    const int wm   = (wid & 1) * 64;
    const int wn   = (wid >> 1) * 32;
    const int bm   = blockIdx.y * 128;
    const int bn   = blockIdx.x * 128;

    const int lrow = tid >> 1;
    const int lk16 = (tid & 1) * 16;

    const __half* Ap = A + (size_t)(bm + lrow) * K + lk16;
    const __half* Wp = W + (size_t)(bn + lrow) * K + lk16;

    uint32_t sAw[GSTG], sBw[GSTG];
    uint32_t aLd[GSTG], bLd[GSTG];
    const int arow = lane & 15;
    const int acol = (lane >> 4) << 3;
    const int brow = (lane & 7) + (((lane >> 4) & 1) << 3);
    const int bcol = ((lane >> 3) & 1) << 3;
    #pragma unroll
    for (int b = 0; b < GSTG; ++b) {
        sAw[b] = smem_u32(gsm + (2 * b    ) * GTILE + lrow * GPAD + lk16);
        sBw[b] = smem_u32(gsm + (2 * b + 1) * GTILE + lrow * GPAD + lk16);
        aLd[b] = smem_u32(gsm + (2 * b    ) * GTILE) + (((wm + arow) * GPAD + acol) << 1);
        bLd[b] = smem_u32(gsm + (2 * b + 1) * GTILE) + (((wn + brow) * GPAD + bcol) << 1);
    }

    const int NS = K >> 5;

    auto issue = [&](int s, int b) {
        const __half* as = Ap + (size_t)s * 32;
        const __half* ws = Wp + (size_t)s * 32;
        CP_ASYNC16(sAw[b],      as);
        CP_ASYNC16(sAw[b] + 16, as + 8);
        CP_ASYNC16(sBw[b],      ws);
        CP_ASYNC16(sBw[b] + 16, ws + 8);
    };

    issue(0, 0); CP_COMMIT();
    issue(1, 1); CP_COMMIT();

    float acc[4][4][4];
    #pragma unroll
    for (int i = 0; i < 4; i++)
        #pragma unroll
        for (int j = 0; j < 4; j++)
            #pragma unroll
            for (int r = 0; r < 4; r++) acc[i][j][r] = 0.f;

    const int MTSTEP = 16 * GPAD * 2;

    for (int s = 0; s < NS; ++s) {
        CP_WAIT(1);
        __syncthreads();

        if (s + 2 < NS) issue(s + 2, (s + 2) % GSTG);
        CP_COMMIT();

        const int pb = s % GSTG;
        const uint32_t aB = aLd[pb], bB = bLd[pb];

        #pragma unroll
        for (int ks = 0; ks < 2; ++ks) {
            const uint32_t ko = ks * 32;
            uint32_t af[4][4], bf[4][2];
            #pragma unroll
            for (int mt = 0; mt < 4; ++mt)
                LDSM_X4(af[mt][0], af[mt][1], af[mt][2], af[mt][3],
                        aB + mt * MTSTEP + ko);
            #pragma unroll
            for (int pr = 0; pr < 2; ++pr)
                LDSM_X4(bf[2*pr][0], bf[2*pr][1], bf[2*pr+1][0], bf[2*pr+1][1],
                        bB + pr * MTSTEP + ko);
            #pragma unroll
            for (int mt = 0; mt < 4; ++mt)
                #pragma unroll
                for (int nt = 0; nt < 4; ++nt)
                    MMA_F16(acc[mt][nt], af[mt], bf[nt]);
        }
    }

    #pragma unroll
    for (int mt = 0; mt < 4; ++mt) {
        const int row = bm + wm + mt * 16 + grp;
        #pragma unroll
        for (int nt = 0; nt < 4; ++nt) {
            const int col = bn + wn + nt * 8 + 2 * qd;
            const float2 bv = *(const float2*)&bias[col];
            float2 o0, o1;
            o0.x = acc[mt][nt][0] + bv.x; o0.y = acc[mt][nt][1] + bv.y;
            o1.x = acc[mt][nt][2] + bv.x; o1.y = acc[mt][nt][3] + bv.y;
            if (RELU) {
                o0.x = fmaxf(o0.x, 0.f); o0.y = fmaxf(o0.y, 0.f);
                o1.x = fmaxf(o1.x, 0.f); o1.y = fmaxf(o1.y, 0.f);
            }
            if (OUTH) {
                *(__half2*)(CH + (size_t)row * N + col)       = __floats2half2_rn(o0.x, o0.y);
                *(__half2*)(CH + (size_t)(row + 8) * N + col) = __floats2half2_rn(o1.x, o1.y);
            } else {
                *(float2*)(C + (size_t)row * N + col)       = o0;
                *(float2*)(C + (size_t)(row + 8) * N + col) = o1;
            }
        }
    }
}

// ---------------------------------------------------------------------------
// mask tile flags (unchanged).
// ---------------------------------------------------------------------------
__global__ __launch_bounds__(256)
void mask_flags(const int* __restrict__ mask, int* __restrict__ flags)
{
    const int idx = blockIdx.x;
    const int qt = idx >> 5, st = idx & 31;
    const int tid = threadIdx.x;
    int ok = 1;
    for (int i = tid; i < 128 * 64; i += 256) {
        int r = qt * 128 + (i >> 6);
        int c = st * 64 + (i & 63);
        ok &= (mask[(size_t)r * LL + c] != 0);
    }
    int all = __syncthreads_and(ok);
    if (tid == 0) flags[idx] = all;
}

// ---------------------------------------------------------------------------
// Flash attention v4: fp16 mma + ldmatrix QKT fragment loads.
// QKT per k16 step: 1 LDSM.x4 (Q A-frag) + 4 LDSM.x4 (8 K B-frags) = 5 LDSM
// vs 20 scalar LDS. Bank-verified at QSH=72 halfs (phases hit 4r..4r+3 = all
// 32 word-banks). PV keeps packed-Vp scalar path. Rest R15/16-exact.
// ---------------------------------------------------------------------------
#define QSH 72
#define VPS 72
#define ATT_SMEM ((128 * QSH + 64 * QSH) * 2 + 32 * VPS * 4)   // 36864 B

__global__ __launch_bounds__(256)
void flash_attn_mma(const __half* __restrict__ qkv, const int* __restrict__ mask,
                    const int* __restrict__ flags, __half* __restrict__ hvals)
{
    extern __shared__ char asm_raw[];
    __half*   Qs = (__half*)asm_raw;                      // [128][QSH]
    __half*   Ks = Qs + 128 * QSH;                        // [64][QSH]
    uint32_t* Vp = (uint32_t*)(Ks + 64 * QSH);            // [32][VPS]

    const int tid  = threadIdx.x;
    const int wid  = tid >> 5, lane = tid & 31;
    const int grp  = lane >> 2, qd = lane & 3;
    const int qt   = blockIdx.x;
    const int head = blockIdx.y;
    const int b    = blockIdx.z;
    const int qbase = qt * 128;
    const int m0   = wid * 16;

    const float QSCALE = 0.125f * 1.44269504088896340736f;

    // ldmatrix lane addresses
    const int lj = lane >> 3, lr7 = lane & 7;
    const uint32_t qLd = smem_u32(Qs) +
        (((m0 + (lj & 1) * 8 + lr7) * QSH + ((lj >> 1) << 3)) << 1);
    uint32_t kLd[4];
    #pragma unroll
    for (int pr = 0; pr < 4; ++pr)
        kLd[pr] = smem_u32(Ks) +
            (((pr * 16 + (lj >> 1) * 8 + lr7) * QSH + ((lj & 1) << 3)) << 1);

    // ---- Q tile: fp16 in, scale, fp16 out ----
    const __half* qp = qkv + ((size_t)(b * LL + qbase)) * (3 * DD) + head * (3 * HD);
    for (int s = tid; s < 128 * 8; s += 256) {
        int r = s >> 3, c = (s & 7) * 8;
        const __half2* src2 = (const __half2*)(qp + (size_t)r * (3 * DD) + c);
        __half2* dst2 = (__half2*)&Qs[r * QSH + c];
        #pragma unroll
        for (int i = 0; i < 4; ++i) {
            float2 f = __half22float2(src2[i]);
            dst2[i] = __floats2half2_rn(f.x * QSCALE, f.y * QSCALE);
        }
    }

    float o[8][4];
    #pragma unroll
    for (int nt = 0; nt < 8; ++nt)
        #pragma unroll
        for (int r = 0; r < 4; ++r) o[nt][r] = 0.f;
    float m_0 = -INFINITY, m_1 = -INFINITY, l_0 = 0.f, l_1 = 0.f;

    const __half* kvbase = qkv + ((size_t)(b * LL)) * (3 * DD) + head * (3 * HD) + HD;

    for (int st = 0; st < LL / 64; ++st) {
        __syncthreads();
        const int sbase = st * 64;

        for (int s = tid; s < 64 * 8; s += 256) {
            int r = s >> 3, c = (s & 7) * 8;
            *(uint4*)&Ks[r * QSH + c] =
                *(const uint4*)(kvbase + (size_t)(sbase + r) * (3 * DD) + c);
        }
        {
            int sp = tid >> 3, c0 = (tid & 7) * 8;
            const __half2* r0 = (const __half2*)(kvbase + (size_t)(sbase + 2 * sp    ) * (3 * DD) + HD + c0);
            const __half2* r1 = (const __half2*)(kvbase + (size_t)(sbase + 2 * sp + 1) * (3 * DD) + HD + c0);
            uint32_t* dst = &Vp[sp * VPS + c0];
            #pragma unroll
            for (int i = 0; i < 4; ++i) {
                __half2 a = r0[i], bb = r1[i];
                dst[2 * i]     = __half_as_ushort(__low2half(a)) |
                                 ((uint32_t)__half_as_ushort(__low2half(bb)) << 16);
                dst[2 * i + 1] = __half_as_ushort(__high2half(a)) |
                                 ((uint32_t)__half_as_ushort(__high2half(bb)) << 16);
            }
        }
        __syncthreads();

        // ---- S' = Qs @ K^T (fp16, ldmatrix frags) ----
        float sacc[8][4];
        #pragma unroll
        for (int nt = 0; nt < 8; ++nt)
            #pragma unroll
            for (int r = 0; r < 4; ++r) sacc[nt][r] = 0.f;

        #pragma unroll
        for (int ks = 0; ks < 4; ++ks) {
            const uint32_t ko = ks * 32;   // 16 halfs
            uint32_t a[4];
            LDSM_X4(a[0], a[1], a[2], a[3], qLd + ko);
            uint32_t bf[8][2];
            #pragma unroll
            for (int pr = 0; pr < 4; ++pr)
                LDSM_X4(bf[2*pr][0], bf[2*pr][1], bf[2*pr+1][0], bf[2*pr+1][1],
                        kLd[pr] + ko);
            #pragma unroll
            for (int nt = 0; nt < 8; ++nt)
                MMA_F16(sacc[nt], a, bf[nt]);
        }

        // ---- mask (slow path only when tile has zeros) ----
        if (flags[qt * 32 + st] == 0) {
            const int r0g = qbase + m0 + grp, r1g = r0g + 8;
            #pragma unroll
            for (int nt = 0; nt < 8; ++nt) {
                const int c0 = sbase + nt * 8 + 2 * qd;
                if (mask[(size_t)r0g * LL + c0    ] == 0) sacc[nt][0] = -INFINITY;
                if (mask[(size_t)r0g * LL + c0 + 1] == 0) sacc[nt][1] = -INFINITY;
                if (mask[(size_t)r1g * LL + c0    ] == 0) sacc[nt][2] = -INFINITY;
                if (mask[(size_t)r1g * LL + c0 + 1] == 0) sacc[nt][3] = -INFINITY;
            }
        }

        // ---- online softmax (exp2 domain) ----
        float rm0 = -INFINITY, rm1 = -INFINITY;
        #pragma unroll
        for (int nt = 0; nt < 8; ++nt) {
            rm0 = fmaxf(rm0, fmaxf(sacc[nt][0], sacc[nt][1]));
            rm1 = fmaxf(rm1, fmaxf(sacc[nt][2], sacc[nt][3]));
        }
        rm0 = fmaxf(rm0, __shfl_xor_sync(0xffffffffu, rm0, 1));
        rm0 = fmaxf(rm0, __shfl_xor_sync(0xffffffffu, rm0, 2));
        rm1 = fmaxf(rm1, __shfl_xor_sync(0xffffffffu, rm1, 1));
        rm1 = fmaxf(rm1, __shfl_xor_sync(0xffffffffu, rm1, 2));
        const float mn0 = fmaxf(m_0, rm0), mn1 = fmaxf(m_1, rm1);
        const float al0 = exp2f(m_0 - mn0), al1 = exp2f(m_1 - mn1);
        m_0 = mn0; m_1 = mn1;

        uint32_t ph[8][2];
        float s0 = 0.f, s1 = 0.f;
        #pragma unroll
        for (int nt = 0; nt < 8; ++nt) {
            __half2 p01 = __floats2half2_rn(exp2f(sacc[nt][0] - mn0),
                                            exp2f(sacc[nt][1] - mn0));
            __half2 p23 = __floats2half2_rn(exp2f(sacc[nt][2] - mn1),
                                            exp2f(sacc[nt][3] - mn1));
            ph[nt][0] = *(uint32_t*)&p01;
            ph[nt][1] = *(uint32_t*)&p23;
            float2 f0 = __half22float2(p01), f1 = __half22float2(p23);
            s0 += f0.x + f0.y; s1 += f1.x + f1.y;
        }
        s0 += __shfl_xor_sync(0xffffffffu, s0, 1);
        s0 += __shfl_xor_sync(0xffffffffu, s0, 2);
        s1 += __shfl_xor_sync(0xffffffffu, s1, 1);
        s1 += __shfl_xor_sync(0xffffffffu, s1, 2);
        l_0 = l_0 * al0 + s0;
        l_1 = l_1 * al1 + s1;
        #pragma unroll
        for (int nt = 0; nt < 8; ++nt) {
            o[nt][0] *= al0; o[nt][1] *= al0;
            o[nt][2] *= al1; o[nt][3] *= al1;
        }

        // ---- O += P @ V (fp16; A-frag = S C-frag, zero shuffles) ----
        #pragma unroll
        for (int ks = 0; ks < 4; ++ks) {
            uint32_t a[4];
            a[0] = ph[2 * ks    ][0];
            a[1] = ph[2 * ks    ][1];
            a[2] = ph[2 * ks + 1][0];
            a[3] = ph[2 * ks + 1][1];
            const int kp = ks * 8;
            #pragma unroll
            for (int nt = 0; nt < 8; ++nt) {
                uint32_t bb[2];
                bb[0] = Vp[(kp + qd    ) * VPS + nt * 8 + grp];
                bb[1] = Vp[(kp + qd + 4) * VPS + nt * 8 + grp];
                MMA_F16(o[nt], a, bb);
            }
        }
    }

    const float li0 = 1.f / l_0, li1 = 1.f / l_1;
    const int r0g = qbase + m0 + grp;
    #pragma unroll
    for (int nt = 0; nt < 8; ++nt) {
        const int col = head * HD + nt * 8 + 2 * qd;
        *(__half2*)&hvals[((size_t)(b * LL + r0g    )) * DD + col] =
            __floats2half2_rn(o[nt][0] * li0, o[nt][1] * li0);
        *(__half2*)&hvals[((size_t)(b * LL + r0g + 8)) * DD + col] =
            __floats2half2_rn(o[nt][2] * li1, o[nt][3] * li1);
    }
}

// ---------------------------------------------------------------------------
// Fused residual-add + LayerNorm; optional fp16 copy of the output.
// ---------------------------------------------------------------------------
template<int WH>
__global__ __launch_bounds__(128)
void add_ln(const float* __restrict__ a, const float* __restrict__ bres,
            const float* __restrict__ g, const float* __restrict__ beta,
            float* __restrict__ out, __half* __restrict__ hout)
{
    const int row = blockIdx.x;
    const int tid = threadIdx.x;

    float4 av = ((const float4*)(a    + (size_t)row * DD))[tid];
    float4 bv = ((const float4*)(bres + (size_t)row * DD))[tid];
    float4 x = make_float4(av.x+bv.x, av.y+bv.y, av.z+bv.z, av.w+bv.w);

    float s  = x.x + x.y + x.z + x.w;
    float ss = x.x*x.x + x.y*x.y + x.z*x.z + x.w*x.w;

    #pragma unroll
    for (int o = 16; o > 0; o >>= 1) {
        s  += __shfl_xor_sync(0xffffffffu, s,  o);
        ss += __shfl_xor_sync(0xffffffffu, ss, o);
    }
    __shared__ float red[2][4];
    const int w = tid >> 5, l = tid & 31;
    if (l == 0) { red[0][w] = s; red[1][w] = ss; }
    __syncthreads();
    s  = red[0][0] + red[0][1] + red[0][2] + red[0][3];
    ss = red[1][0] + red[1][1] + red[1][2] + red[1][3];

    const float mean = s * (1.f / DD);
    const float var  = ss * (1.f / DD) - mean * mean;
    const float rstd = rsqrtf(var + 1e-5f);

    float4 gv = ((const float4*)g)[tid];
    float4 ev = ((const float4*)beta)[tid];
    float4 o;
    o.x = (x.x - mean) * rstd * gv.x + ev.x;
    o.y = (x.y - mean) * rstd * gv.y + ev.y;
    o.z = (x.z - mean) * rstd * gv.z + ev.z;
    o.w = (x.w - mean) * rstd * gv.w + ev.w;
    ((float4*)(out + (size_t)row * DD))[tid] = o;
    if (WH) {
        *(__half2*)(hout + (size_t)row * DD + tid * 4)     = __floats2half2_rn(o.x, o.y);
        *(__half2*)(hout + (size_t)row * DD + tid * 4 + 2) = __floats2half2_rn(o.z, o.w);
    }
}

// ---------------------------------------------------------------------------
extern "C" void kernel_launch(void* const* d_in, const int* in_sizes, int n_in,
                              void* d_out, int out_size)
{
    const float* src    = (const float*)d_in[0];
    const int*   mask   = (const int*)  d_in[1];
    const float* qkv_w  = (const float*)d_in[2];
    const float* qkv_b  = (const float*)d_in[3];
    const float* out_w  = (const float*)d_in[4];
    const float* out_b  = (const float*)d_in[5];
    const float* w1     = (const float*)d_in[6];
    const float* b1     = (const float*)d_in[7];
    const float* w2     = (const float*)d_in[8];
    const float* b2     = (const float*)d_in[9];
    const float* g1     = (const float*)d_in[10];
    const float* beta1  = (const float*)d_in[11];
    const float* g2     = (const float*)d_in[12];
    const float* beta2  = (const float*)d_in[13];
    float* out = (float*)d_out;

    void* p;
    cudaGetSymbolAddress(&p, g_tmp);   float*  tmp   = (float*)p;
    cudaGetSymbolAddress(&p, g_x1);    float*  x1    = (float*)p;
    cudaGetSymbolAddress(&p, g_mflag); int*    mflag = (int*)p;
    cudaGetSymbolAddress(&p, h_qkv);   __half* hqkv  = (__half*)p;
    cudaGetSymbolAddress(&p, h_src);   __half* hsrc  = (__half*)p;
    cudaGetSymbolAddress(&p, h_qkvw);  __half* hqkvw = (__half*)p;
    cudaGetSymbolAddress(&p, h_outw);  __half* houtw = (__half*)p;
    cudaGetSymbolAddress(&p, h_w1);    __half* hw1   = (__half*)p;
    cudaGetSymbolAddress(&p, h_w2);    __half* hw2   = (__half*)p;
    cudaGetSymbolAddress(&p, h_vals);  __half* hvals = (__half*)p;
    cudaGetSymbolAddress(&p, h_x1);    __half* hx1   = (__half*)p;
    cudaGetSymbolAddress(&p, h_ff);    __half* hff   = (__half*)p;

    cudaFuncSetAttribute(mma_gemm<0,0>, cudaFuncAttributeMaxDynamicSharedMemorySize, GEMM_SMEM);
    cudaFuncSetAttribute(mma_gemm<0,1>, cudaFuncAttributeMaxDynamicSharedMemorySize, GEMM_SMEM);
    cudaFuncSetAttribute(mma_gemm<1,1>, cudaFuncAttributeMaxDynamicSharedMemorySize, GEMM_SMEM);
    cudaFuncSetAttribute(flash_attn_mma, cudaFuncAttributeMaxDynamicSharedMemorySize, ATT_SMEM);

    // 0) operand conversions (2 launches) + mask flags
    f2h<<<256, 256>>>(src, hsrc, MR * DD);
    f2h4<<<160, 256>>>(qkv_w, hqkvw, 3 * DD * DD,
                       out_w, houtw, DD * DD,
                       w1,    hw1,   DFF * DD,
                       w2,    hw2,   DD * DFF);
    mask_flags<<<512, 256>>>(mask, mflag);

    // 1) QKV projection (fp16 in, fp16 out)
    mma_gemm<0,1><<<dim3((3*DD)/128, MR/128), 256, GEMM_SMEM>>>(
        hsrc, hqkvw, qkv_b, nullptr, hqkv, MR, 3*DD, DD);

    // 2) flash attention (all-fp16 mma + ldmatrix) -> h_vals
    flash_attn_mma<<<dim3(LL/128, HH, BB), 256, ATT_SMEM>>>(hqkv, mask, mflag, hvals);

    // 3) output projection (fp16 in, fp32 out)
    mma_gemm<0,0><<<dim3(DD/128, MR/128), 256, GEMM_SMEM>>>(
        hvals, houtw, out_b, tmp, nullptr, MR, DD, DD);

    // 4) x1 = LN(src + proj), also fp16 copy
    add_ln<1><<<MR, 128>>>(src, tmp, g1, beta1, x1, hx1);

    // 5) FFN1 + ReLU (fp16 in, fp16 out)
    mma_gemm<1,1><<<dim3(DFF/128, MR/128), 256, GEMM_SMEM>>>(
        hx1, hw1, b1, nullptr, hff, MR, DFF, DD);

    // 6) FFN2 (fp16 in, fp32 out)
    mma_gemm<0,0><<<dim3(DD/128, MR/128), 256, GEMM_SMEM>>>(
        hff, hw2, b2, tmp, nullptr, MR, DD, DFF);

    // 7) out = LN(x1 + ffn2)
    add_ln<0><<<MR, 128>>>(x1, tmp, g2, beta2, out, nullptr);
}